// round 1
// baseline (speedup 1.0000x reference)
#include <cuda_runtime.h>
#include <cstddef>

// Problem constants
#define Bv   32
#define Nv   1025
#define DIMv 768
#define Hv   12
#define Dv   64
#define M1   (Bv * Nv)          // 32800 tokens
#define G3   (3 * Hv * Dv)      // 2304

// -------- scratch (device globals; no allocation allowed) --------
__device__ float g_qkv [(size_t)M1 * G3];           // (b, n, 3, h, d)   302 MB
__device__ float g_qf  [(size_t)Bv * Hv * Nv * Dv]; // (b, h, n, j)      100 MB
__device__ float g_kf  [(size_t)Bv * Hv * Nv * Dv]; //                   100 MB
__device__ float g_ctx [(size_t)Bv * Hv * Dv * Dv]; // (bh, d, e)          6 MB
__device__ float g_ksum[(size_t)Bv * Hv * Dv];
__device__ float g_attn[(size_t)M1 * DIMv];         // (b, n, h*d)       100 MB

// ============================================================================
// Tiled SGEMM:  C[M,Nc] = A[M,K] * B[Nc,K]^T (+ bias[Nc])
// BM=BN=128, BK=16, 256 threads, 8x8 per thread.
// Nc and K must be multiples of 128/16 (true here); M is guarded.
// ============================================================================
template <bool BIAS>
__global__ __launch_bounds__(256, 2)
void gemm_nt(const float* __restrict__ A, const float* __restrict__ Bm,
             const float* __restrict__ bias, float* __restrict__ C,
             int M, int Nc, int K) {
    constexpr int BM = 128, BN = 128, BK = 16;
    __shared__ float As[BK][BM];
    __shared__ float Bs[BK][BN];

    const int tid = threadIdx.x;
    const int tx = tid & 15;        // 0..15 -> N direction
    const int ty = tid >> 4;        // 0..15 -> M direction
    const int row0 = blockIdx.y * BM;
    const int col0 = blockIdx.x * BN;

    float acc[8][8] = {};

    for (int k0 = 0; k0 < K; k0 += BK) {
        // ---- load A tile (BM x BK) as float4, store k-major ----
        #pragma unroll
        for (int l = 0; l < 2; ++l) {
            int f4 = tid + l * 256;                 // 0..511
            int r  = f4 >> 2;                       // row in tile (16 floats = 4 f4 per row)
            int kc = (f4 & 3) * 4;
            float4 v;
            int gr = row0 + r;
            if (gr < M) v = *reinterpret_cast<const float4*>(&A[(size_t)gr * K + k0 + kc]);
            else        v = make_float4(0.f, 0.f, 0.f, 0.f);
            As[kc + 0][r] = v.x; As[kc + 1][r] = v.y;
            As[kc + 2][r] = v.z; As[kc + 3][r] = v.w;
        }
        // ---- load B tile (BN x BK) ----
        #pragma unroll
        for (int l = 0; l < 2; ++l) {
            int f4 = tid + l * 256;
            int r  = f4 >> 2;
            int kc = (f4 & 3) * 4;
            float4 v = *reinterpret_cast<const float4*>(&Bm[(size_t)(col0 + r) * K + k0 + kc]);
            Bs[kc + 0][r] = v.x; Bs[kc + 1][r] = v.y;
            Bs[kc + 2][r] = v.z; Bs[kc + 3][r] = v.w;
        }
        __syncthreads();

        #pragma unroll
        for (int kk = 0; kk < BK; ++kk) {
            float a[8], b[8];
            const float4* a4 = reinterpret_cast<const float4*>(&As[kk][ty * 8]);
            const float4* b4 = reinterpret_cast<const float4*>(&Bs[kk][tx * 8]);
            float4 a0 = a4[0], a1 = a4[1];
            float4 b0 = b4[0], b1 = b4[1];
            a[0]=a0.x;a[1]=a0.y;a[2]=a0.z;a[3]=a0.w;a[4]=a1.x;a[5]=a1.y;a[6]=a1.z;a[7]=a1.w;
            b[0]=b0.x;b[1]=b0.y;b[2]=b0.z;b[3]=b0.w;b[4]=b1.x;b[5]=b1.y;b[6]=b1.z;b[7]=b1.w;
            #pragma unroll
            for (int i = 0; i < 8; ++i)
                #pragma unroll
                for (int j = 0; j < 8; ++j)
                    acc[i][j] += a[i] * b[j];
        }
        __syncthreads();
    }

    #pragma unroll
    for (int i = 0; i < 8; ++i) {
        int gr = row0 + ty * 8 + i;
        if (gr >= M) continue;
        #pragma unroll
        for (int j = 0; j < 8; ++j) {
            int gc = col0 + tx * 8 + j;
            float v = acc[i][j];
            if (BIAS) v += bias[gc];
            C[(size_t)gr * Nc + gc] = v;
        }
    }
}

// ============================================================================
// RoPE (skip CLS token 0) + performer feature map (project, relu, +1e-6).
// grid (Nv, Hv, Bv), 128 threads: tid<64 handles q, tid>=64 handles k.
// ============================================================================
__global__ __launch_bounds__(128)
void rope_feat(const float* __restrict__ qkv, const float* __restrict__ proj,
               const float* __restrict__ fcos, const float* __restrict__ fsin,
               float* __restrict__ qf, float* __restrict__ kf) {
    const int n = blockIdx.x, h = blockIdx.y, b = blockIdx.z;
    const int tid  = threadIdx.x;
    const int half = tid >> 6;       // 0=q, 1=k
    const int lane = tid & 63;       // d when loading, j when projecting
    __shared__ float raw[2][Dv];
    __shared__ float vec[2][Dv];
    const float scale = 0.35355339059327379f;  // 64^-0.25

    size_t base = ((size_t)(b * Nv + n) * 3 + half) * (Hv * Dv) + h * Dv + lane;
    raw[half][lane] = qkv[base];
    __syncthreads();

    float val;
    if (n == 0) {
        val = raw[half][lane];
    } else {
        int i  = lane >> 1;
        float c = fcos[(size_t)(n - 1) * (Dv / 2) + i];
        float s = fsin[(size_t)(n - 1) * (Dv / 2) + i];
        float ev = raw[half][lane & ~1];
        float od = raw[half][lane |  1];
        val = (lane & 1) ? (ev * s + od * c) : (ev * c - od * s);
    }
    vec[half][lane] = val * scale;
    __syncthreads();

    float accv = 0.f;
    const float* pr = proj + (size_t)lane * Dv;
    #pragma unroll 8
    for (int d = 0; d < Dv; ++d) accv += vec[half][d] * pr[d];
    accv = fmaxf(accv, 0.f) + 1e-6f;

    size_t o = (((size_t)b * Hv + h) * Nv + n) * Dv + lane;
    (half == 0 ? qf : kf)[o] = accv;
}

// ============================================================================
// context[bh,d,e] = sum_n kf[n,d] * v[n,e];  k_sum[bh,d] = sum_n kf[n,d]
// grid (Bv*Hv), 256 threads, 4x4 per thread, n-tile = 8.
// ============================================================================
__global__ __launch_bounds__(256)
void ctx_kernel(const float* __restrict__ kf, const float* __restrict__ qkv,
                float* __restrict__ ctx, float* __restrict__ ksum) {
    constexpr int TILE = 8;
    __shared__ float ks[TILE][Dv];
    __shared__ float vs[TILE][Dv];

    const int bh = blockIdx.x;
    const int b = bh / Hv, h = bh % Hv;
    const int tid = threadIdx.x;
    const int tx = tid & 15;    // e group
    const int ty = tid >> 4;    // d group

    // one float4 load per thread per tile: which(1) | row(3) | col4(4)
    const int which = tid >> 7;          // 0: kf, 1: v
    const int rr    = (tid >> 4) & 7;
    const int c4    = (tid & 15) * 4;

    float acc[4][4] = {};
    float ksl = 0.f;

    for (int n0 = 0; n0 < Nv; n0 += TILE) {
        int n = n0 + rr;
        float4 v;
        if (n < Nv) {
            if (which == 0)
                v = *reinterpret_cast<const float4*>(
                        &kf[(((size_t)b * Hv + h) * Nv + n) * Dv + c4]);
            else
                v = *reinterpret_cast<const float4*>(
                        &qkv[(((size_t)(b * Nv + n)) * 3 + 2) * (Hv * Dv) + h * Dv + c4]);
        } else {
            v = make_float4(0.f, 0.f, 0.f, 0.f);
        }
        __syncthreads();   // previous tile fully consumed
        float* dst = (which == 0) ? &ks[rr][c4] : &vs[rr][c4];
        dst[0] = v.x; dst[1] = v.y; dst[2] = v.z; dst[3] = v.w;
        __syncthreads();

        #pragma unroll
        for (int r = 0; r < TILE; ++r) {
            float a[4], bb[4];
            #pragma unroll
            for (int i = 0; i < 4; ++i) a[i]  = ks[r][ty * 4 + i];
            #pragma unroll
            for (int j = 0; j < 4; ++j) bb[j] = vs[r][tx * 4 + j];
            #pragma unroll
            for (int i = 0; i < 4; ++i)
                #pragma unroll
                for (int j = 0; j < 4; ++j)
                    acc[i][j] += a[i] * bb[j];
        }
        if (tid < Dv) {
            #pragma unroll
            for (int r = 0; r < TILE; ++r) ksl += ks[r][tid];
        }
    }

    #pragma unroll
    for (int i = 0; i < 4; ++i)
        #pragma unroll
        for (int j = 0; j < 4; ++j)
            ctx[((size_t)bh * Dv + ty * 4 + i) * Dv + tx * 4 + j] = acc[i][j];
    if (tid < Dv) ksum[(size_t)bh * Dv + tid] = ksl;
}

// ============================================================================
// out[b,n,h*64+e] = (sum_d ctx[d,e]*qf[n,d]) / (sum_d qf[n,d]*ksum[d])
// grid (Bv*Hv, NCHUNK), 256 threads = 4 groups of 64, one token per group.
// ============================================================================
#define NCHUNK 8
__global__ __launch_bounds__(256)
void out_kernel(const float* __restrict__ qf, const float* __restrict__ ctx,
                const float* __restrict__ ksum, float* __restrict__ attn) {
    __shared__ float sctx[Dv][Dv];
    __shared__ float sks[Dv];
    __shared__ float sqf[4][Dv];

    const int bh = blockIdx.x;
    const int b = bh / Hv, h = bh % Hv;
    const int tid = threadIdx.x;
    const int g = tid >> 6, e = tid & 63;

    for (int l = tid; l < Dv * Dv / 4; l += 256) {
        float4 v = reinterpret_cast<const float4*>(ctx + (size_t)bh * Dv * Dv)[l];
        reinterpret_cast<float4*>(&sctx[0][0])[l] = v;
    }
    if (tid < Dv) sks[tid] = ksum[(size_t)bh * Dv + tid];
    __syncthreads();

    const int chunk  = (Nv + NCHUNK - 1) / NCHUNK;   // 129
    const int nstart = blockIdx.y * chunk;
    const int nend   = min(nstart + chunk, Nv);

    for (int n0 = nstart; n0 < nend; n0 += 4) {
        int n = n0 + g;
        __syncthreads();
        if (n < nend) sqf[g][e] = qf[(((size_t)b * Hv + h) * Nv + n) * Dv + e];
        __syncthreads();
        if (n < nend) {
            float denom = 0.f, accv = 0.f;
            #pragma unroll 8
            for (int d = 0; d < Dv; ++d) {
                float q = sqf[g][d];
                denom += q * sks[d];
                accv  += q * sctx[d][e];
            }
            attn[((size_t)(b * Nv + n)) * DIMv + h * Dv + e] = accv / denom;
        }
    }
}

// ============================================================================
// launcher
// ============================================================================
extern "C" void kernel_launch(void* const* d_in, const int* in_sizes, int n_in,
                              void* d_out, int out_size) {
    const float* x     = (const float*)d_in[0];  // (32,1025,768)
    const float* W_qkv = (const float*)d_in[1];  // (2304,768)
    const float* W_out = (const float*)d_in[2];  // (768,768)
    const float* b_out = (const float*)d_in[3];  // (768,)
    const float* proj  = (const float*)d_in[4];  // (64,64)
    const float* fcos  = (const float*)d_in[5];  // (1024,32)
    const float* fsin  = (const float*)d_in[6];  // (1024,32)
    float* out = (float*)d_out;

    float *p_qkv, *p_qf, *p_kf, *p_ctx, *p_ksum, *p_attn;
    cudaGetSymbolAddress((void**)&p_qkv,  g_qkv);
    cudaGetSymbolAddress((void**)&p_qf,   g_qf);
    cudaGetSymbolAddress((void**)&p_kf,   g_kf);
    cudaGetSymbolAddress((void**)&p_ctx,  g_ctx);
    cudaGetSymbolAddress((void**)&p_ksum, g_ksum);
    cudaGetSymbolAddress((void**)&p_attn, g_attn);

    // 1) QKV projection: (32800 x 768) * (2304 x 768)^T
    {
        dim3 grid(G3 / 128, (M1 + 127) / 128);
        gemm_nt<false><<<grid, 256>>>(x, W_qkv, nullptr, p_qkv, M1, G3, DIMv);
    }
    // 2) RoPE + feature map for q and k
    {
        dim3 grid(Nv, Hv, Bv);
        rope_feat<<<grid, 128>>>(p_qkv, proj, fcos, fsin, p_qf, p_kf);
    }
    // 3) context + k_sum
    ctx_kernel<<<Bv * Hv, 256>>>(p_kf, p_qkv, p_ctx, p_ksum);
    // 4) per-token output contraction
    {
        dim3 grid(Bv * Hv, NCHUNK);
        out_kernel<<<grid, 256>>>(p_qf, p_ctx, p_ksum, p_attn);
    }
    // 5) output projection + bias: (32800 x 768) * (768 x 768)^T + b
    {
        dim3 grid(DIMv / 128, (M1 + 127) / 128);
        gemm_nt<true><<<grid, 256>>>(p_attn, W_out, b_out, out, M1, DIMv, DIMv);
    }
}

// round 2
// speedup vs baseline: 1.1023x; 1.1023x over previous
#include <cuda_runtime.h>
#include <cstddef>

// Problem constants
#define Bv   32
#define Nv   1025
#define DIMv 768
#define Hv   12
#define Dv   64
#define M1   (Bv * Nv)          // 32800 tokens
#define G3   (3 * Hv * Dv)      // 2304

// -------- scratch (device globals; no allocation allowed) --------
__device__ float g_qkv [(size_t)M1 * G3];           // (b, n, 3, h, d)
__device__ float g_qf  [(size_t)Bv * Hv * Nv * Dv]; // (b, h, n, j)
__device__ float g_kf  [(size_t)Bv * Hv * Nv * Dv];
__device__ float g_ctx [(size_t)Bv * Hv * Dv * Dv]; // (bh, d, e)
__device__ float g_ksum[(size_t)Bv * Hv * Dv];
__device__ float g_attn[(size_t)M1 * DIMv];         // (b, n, h*d)

// ============================================================================
// tf32 helpers
// ============================================================================
__device__ __forceinline__ float tf32_rna(float x) {
    unsigned r;
    asm("cvt.rna.tf32.f32 %0, %1;" : "=r"(r) : "f"(x));
    return __uint_as_float(r);
}
__device__ __forceinline__ unsigned f2b(float x) { return __float_as_uint(x); }

__device__ __forceinline__ void mma8(float* d, const unsigned* a, const unsigned* b) {
    asm volatile(
        "mma.sync.aligned.m16n8k8.row.col.f32.tf32.tf32.f32 "
        "{%0,%1,%2,%3},{%4,%5,%6,%7},{%8,%9},{%0,%1,%2,%3};"
        : "+f"(d[0]), "+f"(d[1]), "+f"(d[2]), "+f"(d[3])
        : "r"(a[0]), "r"(a[1]), "r"(a[2]), "r"(a[3]), "r"(b[0]), "r"(b[1]));
}

// ============================================================================
// Tensor-core GEMM (3xTF32 = ~fp32 accuracy):
//   C[M,Nc] = A[M,K] * B[Nc,K]^T (+ bias)
// BM=BN=128, BK=16, 256 threads (8 warps, warp tile 64x32).
// Nc % 128 == 0 and K % 16 == 0 required (true for both call sites).
// Both smem tiles stored [row][20] (pad 4) -> conflict-free fragment loads.
// ============================================================================
#define BM  128
#define BN  128
#define BKv 16
#define BKP 20

template <bool BIAS>
__global__ __launch_bounds__(256, 2)
void gemm_tf32(const float* __restrict__ A, const float* __restrict__ Bm,
               const float* __restrict__ bias, float* __restrict__ C,
               int M, int Nc, int K) {
    __shared__ float As[2][BM][BKP];
    __shared__ float Bs[2][BN][BKP];

    const int tid  = threadIdx.x;
    const int warp = tid >> 5, lane = tid & 31;
    const int qr = lane >> 2, qc = lane & 3;
    const int row0 = blockIdx.y * BM;
    const int col0 = blockIdx.x * BN;
    const int wm = (warp >> 2) * 64;   // 0 / 64
    const int wn = (warp & 3) * 32;    // 0 / 32 / 64 / 96

    float acc[4][4][4];
    #pragma unroll
    for (int i = 0; i < 4; ++i)
        #pragma unroll
        for (int j = 0; j < 4; ++j)
            #pragma unroll
            for (int k = 0; k < 4; ++k) acc[i][j][k] = 0.f;

    const int nk = K / BKv;

    // ---- async staging of one BK tile into buffer `buf` ----
    auto stage = [&](int t, int buf) {
        const int k0 = t * BKv;
        #pragma unroll
        for (int l = 0; l < 2; ++l) {
            int f4 = tid + l * 256;      // 0..511
            int r  = f4 >> 2;            // tile row
            int q  = (f4 & 3) * 4;       // k offset (float4)
            {   // A (guard M rows with zfill)
                int gr = row0 + r;
                int p  = (gr < M) ? 16 : 0;
                const float* src = A + (size_t)(gr < M ? gr : M - 1) * K + k0 + q;
                unsigned d = (unsigned)__cvta_generic_to_shared(&As[buf][r][q]);
                asm volatile("cp.async.cg.shared.global [%0], [%1], 16, %2;"
                             :: "r"(d), "l"(src), "r"(p));
            }
            {   // B (Nc multiple of 128 -> unguarded)
                const float* src = Bm + (size_t)(col0 + r) * K + k0 + q;
                unsigned d = (unsigned)__cvta_generic_to_shared(&Bs[buf][r][q]);
                asm volatile("cp.async.cg.shared.global [%0], [%1], 16;"
                             :: "r"(d), "l"(src));
            }
        }
    };

    stage(0, 0);
    asm volatile("cp.async.commit_group;");

    for (int t = 0; t < nk; ++t) {
        const int buf = t & 1;
        if (t + 1 < nk) stage(t + 1, buf ^ 1);
        asm volatile("cp.async.commit_group;");
        asm volatile("cp.async.wait_group 1;");
        __syncthreads();

        #pragma unroll
        for (int kc = 0; kc < BKv; kc += 8) {
            // B fragments for 4 n-tiles (hi/lo)
            unsigned bh[4][2], bl[4][2];
            #pragma unroll
            for (int ni = 0; ni < 4; ++ni) {
                int n = wn + ni * 8 + qr;
                float b0 = Bs[buf][n][kc + qc];
                float b1 = Bs[buf][n][kc + qc + 4];
                float h0 = tf32_rna(b0), h1 = tf32_rna(b1);
                bh[ni][0] = f2b(h0);      bh[ni][1] = f2b(h1);
                bl[ni][0] = f2b(b0 - h0); bl[ni][1] = f2b(b1 - h1);
            }
            #pragma unroll
            for (int mi = 0; mi < 4; ++mi) {
                int m = wm + mi * 16;
                float a0 = As[buf][m + qr][kc + qc];
                float a1 = As[buf][m + 8 + qr][kc + qc];
                float a2 = As[buf][m + qr][kc + qc + 4];
                float a3 = As[buf][m + 8 + qr][kc + qc + 4];
                float h0 = tf32_rna(a0), h1 = tf32_rna(a1);
                float h2 = tf32_rna(a2), h3 = tf32_rna(a3);
                unsigned ah[4] = {f2b(h0), f2b(h1), f2b(h2), f2b(h3)};
                unsigned al[4] = {f2b(a0 - h0), f2b(a1 - h1),
                                  f2b(a2 - h2), f2b(a3 - h3)};
                // 3xTF32: hi*hi, hi*lo, lo*hi (independent acc across ni)
                #pragma unroll
                for (int ni = 0; ni < 4; ++ni) mma8(acc[mi][ni], ah, bh[ni]);
                #pragma unroll
                for (int ni = 0; ni < 4; ++ni) mma8(acc[mi][ni], ah, bl[ni]);
                #pragma unroll
                for (int ni = 0; ni < 4; ++ni) mma8(acc[mi][ni], al, bh[ni]);
            }
        }
        __syncthreads();
    }

    // ---- epilogue ----
    #pragma unroll
    for (int mi = 0; mi < 4; ++mi) {
        #pragma unroll
        for (int ni = 0; ni < 4; ++ni) {
            int gr = row0 + wm + mi * 16 + qr;
            int gc = col0 + wn + ni * 8 + 2 * qc;
            float b0 = 0.f, b1 = 0.f;
            if (BIAS) { b0 = bias[gc]; b1 = bias[gc + 1]; }
            if (gr < M) {
                C[(size_t)gr * Nc + gc]     = acc[mi][ni][0] + b0;
                C[(size_t)gr * Nc + gc + 1] = acc[mi][ni][1] + b1;
            }
            if (gr + 8 < M) {
                C[(size_t)(gr + 8) * Nc + gc]     = acc[mi][ni][2] + b0;
                C[(size_t)(gr + 8) * Nc + gc + 1] = acc[mi][ni][3] + b1;
            }
        }
    }
}

// ============================================================================
// RoPE (skip CLS token 0) + performer feature map (unchanged from R1 pass).
// ============================================================================
__global__ __launch_bounds__(128)
void rope_feat(const float* __restrict__ qkv, const float* __restrict__ proj,
               const float* __restrict__ fcos, const float* __restrict__ fsin,
               float* __restrict__ qf, float* __restrict__ kf) {
    const int n = blockIdx.x, h = blockIdx.y, b = blockIdx.z;
    const int tid  = threadIdx.x;
    const int half = tid >> 6;
    const int lane = tid & 63;
    __shared__ float raw[2][Dv];
    __shared__ float vec[2][Dv];
    const float scale = 0.35355339059327379f;  // 64^-0.25

    size_t base = ((size_t)(b * Nv + n) * 3 + half) * (Hv * Dv) + h * Dv + lane;
    raw[half][lane] = qkv[base];
    __syncthreads();

    float val;
    if (n == 0) {
        val = raw[half][lane];
    } else {
        int i  = lane >> 1;
        float c = fcos[(size_t)(n - 1) * (Dv / 2) + i];
        float s = fsin[(size_t)(n - 1) * (Dv / 2) + i];
        float ev = raw[half][lane & ~1];
        float od = raw[half][lane |  1];
        val = (lane & 1) ? (ev * s + od * c) : (ev * c - od * s);
    }
    vec[half][lane] = val * scale;
    __syncthreads();

    float accv = 0.f;
    const float* pr = proj + (size_t)lane * Dv;
    #pragma unroll 8
    for (int d = 0; d < Dv; ++d) accv += vec[half][d] * pr[d];
    accv = fmaxf(accv, 0.f) + 1e-6f;

    size_t o = (((size_t)b * Hv + h) * Nv + n) * Dv + lane;
    (half == 0 ? qf : kf)[o] = accv;
}

// ============================================================================
// context + k_sum, split 8-way over n with atomic accumulation.
// grid (Bv*Hv, CSPLIT), 256 threads.
// ============================================================================
#define CSPLIT 8
__global__ __launch_bounds__(256)
void ctx_kernel(const float* __restrict__ kf, const float* __restrict__ qkv,
                float* __restrict__ ctx, float* __restrict__ ksum) {
    constexpr int TILE = 8;
    __shared__ float ks[TILE][Dv];
    __shared__ float vs[TILE][Dv];

    const int bh = blockIdx.x;
    const int b = bh / Hv, h = bh % Hv;
    const int tid = threadIdx.x;
    const int tx = tid & 15;
    const int ty = tid >> 4;

    const int chunk  = (Nv + CSPLIT - 1) / CSPLIT;   // 129
    const int nstart = blockIdx.y * chunk;
    const int nend   = min(nstart + chunk, Nv);

    const int which = tid >> 7;
    const int rr    = (tid >> 4) & 7;
    const int c4    = (tid & 15) * 4;

    float acc[4][4] = {};
    float ksl = 0.f;

    for (int n0 = nstart; n0 < nend; n0 += TILE) {
        int n = n0 + rr;
        float4 v;
        if (n < nend) {
            if (which == 0)
                v = *reinterpret_cast<const float4*>(
                        &kf[(((size_t)b * Hv + h) * Nv + n) * Dv + c4]);
            else
                v = *reinterpret_cast<const float4*>(
                        &qkv[(((size_t)(b * Nv + n)) * 3 + 2) * (Hv * Dv) + h * Dv + c4]);
        } else {
            v = make_float4(0.f, 0.f, 0.f, 0.f);
        }
        __syncthreads();
        float* dst = (which == 0) ? &ks[rr][c4] : &vs[rr][c4];
        dst[0] = v.x; dst[1] = v.y; dst[2] = v.z; dst[3] = v.w;
        __syncthreads();

        #pragma unroll
        for (int r = 0; r < TILE; ++r) {
            float a[4], bb[4];
            #pragma unroll
            for (int i = 0; i < 4; ++i) a[i]  = ks[r][ty * 4 + i];
            #pragma unroll
            for (int j = 0; j < 4; ++j) bb[j] = vs[r][tx * 4 + j];
            #pragma unroll
            for (int i = 0; i < 4; ++i)
                #pragma unroll
                for (int j = 0; j < 4; ++j)
                    acc[i][j] += a[i] * bb[j];
        }
        if (tid < Dv) {
            #pragma unroll
            for (int r = 0; r < TILE; ++r) ksl += ks[r][tid];
        }
    }

    #pragma unroll
    for (int i = 0; i < 4; ++i)
        #pragma unroll
        for (int j = 0; j < 4; ++j)
            atomicAdd(&ctx[((size_t)bh * Dv + ty * 4 + i) * Dv + tx * 4 + j],
                      acc[i][j]);
    if (tid < Dv) atomicAdd(&ksum[(size_t)bh * Dv + tid], ksl);
}

// ============================================================================
// out[b,n,h*64+e] = (sum_d ctx[d,e]*qf[n,d]) / (sum_d qf[n,d]*ksum[d])
// ============================================================================
#define NCHUNK 8
__global__ __launch_bounds__(256)
void out_kernel(const float* __restrict__ qf, const float* __restrict__ ctx,
                const float* __restrict__ ksum, float* __restrict__ attn) {
    __shared__ float sctx[Dv][Dv];
    __shared__ float sks[Dv];
    __shared__ float sqf[4][Dv];

    const int bh = blockIdx.x;
    const int b = bh / Hv, h = bh % Hv;
    const int tid = threadIdx.x;
    const int g = tid >> 6, e = tid & 63;

    for (int l = tid; l < Dv * Dv / 4; l += 256) {
        float4 v = reinterpret_cast<const float4*>(ctx + (size_t)bh * Dv * Dv)[l];
        reinterpret_cast<float4*>(&sctx[0][0])[l] = v;
    }
    if (tid < Dv) sks[tid] = ksum[(size_t)bh * Dv + tid];
    __syncthreads();

    const int chunk  = (Nv + NCHUNK - 1) / NCHUNK;
    const int nstart = blockIdx.y * chunk;
    const int nend   = min(nstart + chunk, Nv);

    for (int n0 = nstart; n0 < nend; n0 += 4) {
        int n = n0 + g;
        __syncthreads();
        if (n < nend) sqf[g][e] = qf[(((size_t)b * Hv + h) * Nv + n) * Dv + e];
        __syncthreads();
        if (n < nend) {
            float denom = 0.f, accv = 0.f;
            #pragma unroll 8
            for (int d = 0; d < Dv; ++d) {
                float q = sqf[g][d];
                denom += q * sks[d];
                accv  += q * sctx[d][e];
            }
            attn[((size_t)(b * Nv + n)) * DIMv + h * Dv + e] = accv / denom;
        }
    }
}

// ============================================================================
// launcher
// ============================================================================
extern "C" void kernel_launch(void* const* d_in, const int* in_sizes, int n_in,
                              void* d_out, int out_size) {
    const float* x     = (const float*)d_in[0];
    const float* W_qkv = (const float*)d_in[1];
    const float* W_out = (const float*)d_in[2];
    const float* b_out = (const float*)d_in[3];
    const float* proj  = (const float*)d_in[4];
    const float* fcos  = (const float*)d_in[5];
    const float* fsin  = (const float*)d_in[6];
    float* out = (float*)d_out;

    float *p_qkv, *p_qf, *p_kf, *p_ctx, *p_ksum, *p_attn;
    cudaGetSymbolAddress((void**)&p_qkv,  g_qkv);
    cudaGetSymbolAddress((void**)&p_qf,   g_qf);
    cudaGetSymbolAddress((void**)&p_kf,   g_kf);
    cudaGetSymbolAddress((void**)&p_ctx,  g_ctx);
    cudaGetSymbolAddress((void**)&p_ksum, g_ksum);
    cudaGetSymbolAddress((void**)&p_attn, g_attn);

    // 1) QKV projection (tensor cores, 3xTF32)
    {
        dim3 grid(G3 / BN, (M1 + BM - 1) / BM);
        gemm_tf32<false><<<grid, 256>>>(x, W_qkv, nullptr, p_qkv, M1, G3, DIMv);
    }
    // 2) RoPE + feature map
    {
        dim3 grid(Nv, Hv, Bv);
        rope_feat<<<grid, 128>>>(p_qkv, proj, fcos, fsin, p_qf, p_kf);
    }
    // 3) context + k_sum (zero, then atomic-accumulate 8 n-slices)
    cudaMemsetAsync(p_ctx,  0, (size_t)Bv * Hv * Dv * Dv * sizeof(float));
    cudaMemsetAsync(p_ksum, 0, (size_t)Bv * Hv * Dv * sizeof(float));
    {
        dim3 grid(Bv * Hv, CSPLIT);
        ctx_kernel<<<grid, 256>>>(p_kf, p_qkv, p_ctx, p_ksum);
    }
    // 4) per-token output contraction
    {
        dim3 grid(Bv * Hv, NCHUNK);
        out_kernel<<<grid, 256>>>(p_qf, p_ctx, p_ksum, p_attn);
    }
    // 5) output projection + bias (tensor cores, 3xTF32)
    {
        dim3 grid(DIMv / BN, (M1 + BM - 1) / BM);
        gemm_tf32<true><<<grid, 256>>>(p_attn, W_out, b_out, out, M1, DIMv, DIMv);
    }
}

// round 5
// speedup vs baseline: 1.1185x; 1.0147x over previous
#include <cuda_runtime.h>
#include <cuda_bf16.h>
#include <cstdint>
#include <cstddef>

// Problem constants
#define Bv   32
#define Nv   1025
#define DIMv 768
#define Hv   12
#define Dv   64
#define M1   (Bv * Nv)          // 32800 tokens
#define G3   (3 * Hv * Dv)      // 2304

// -------- scratch (device globals; no allocation allowed) --------
__device__ float g_qkv [(size_t)M1 * G3];
__device__ float g_qf  [(size_t)Bv * Hv * Nv * Dv];
__device__ float g_kf  [(size_t)Bv * Hv * Nv * Dv];
__device__ float g_ctx [(size_t)Bv * Hv * Dv * Dv];
__device__ float g_ksum[(size_t)Bv * Hv * Dv];
// bf16 hi/lo split planes
__device__ __nv_bfloat16 g_xhi [(size_t)M1 * DIMv],   g_xlo [(size_t)M1 * DIMv];
__device__ __nv_bfloat16 g_wqhi[(size_t)G3 * DIMv],   g_wqlo[(size_t)G3 * DIMv];
__device__ __nv_bfloat16 g_wohi[(size_t)DIMv * DIMv], g_wolo[(size_t)DIMv * DIMv];
__device__ __nv_bfloat16 g_ahi [(size_t)M1 * DIMv],   g_alo [(size_t)M1 * DIMv];

// ============================================================================
// helpers (baseline PTX only: cp.async + ldmatrix + mma.sync)
// ============================================================================
__device__ __forceinline__ uint32_t s2u(const void* p) {
    uint32_t a;
    asm("{ .reg .u64 t; cvta.to.shared.u64 t, %1; cvt.u32.u64 %0, t; }"
        : "=r"(a) : "l"(p));
    return a;
}
__device__ __forceinline__ void cp16(uint32_t dst, const void* src) {
    asm volatile("cp.async.cg.shared.global [%0], [%1], 16;"
                 :: "r"(dst), "l"(src) : "memory");
}
__device__ __forceinline__ void cp16p(uint32_t dst, const void* src, int p) {
    asm volatile("cp.async.cg.shared.global [%0], [%1], 16, %2;"
                 :: "r"(dst), "l"(src), "r"(p) : "memory");
}
#define CPCOMMIT() asm volatile("cp.async.commit_group;" ::: "memory")
__device__ __forceinline__ void cpwait(int n) {
    if (n >= 2)      asm volatile("cp.async.wait_group 2;" ::: "memory");
    else if (n == 1) asm volatile("cp.async.wait_group 1;" ::: "memory");
    else             asm volatile("cp.async.wait_group 0;" ::: "memory");
}
__device__ __forceinline__ void ldm4(uint32_t* r, uint32_t a) {
    asm volatile("ldmatrix.sync.aligned.m8n8.x4.shared.b16 {%0,%1,%2,%3}, [%4];"
                 : "=r"(r[0]), "=r"(r[1]), "=r"(r[2]), "=r"(r[3]) : "r"(a));
}
__device__ __forceinline__ void ldm2(uint32_t* r, uint32_t a) {
    asm volatile("ldmatrix.sync.aligned.m8n8.x2.shared.b16 {%0,%1}, [%2];"
                 : "=r"(r[0]), "=r"(r[1]) : "r"(a));
}
__device__ __forceinline__ void mma16816(float* d, const uint32_t* a,
                                         const uint32_t* b) {
    asm volatile(
        "mma.sync.aligned.m16n8k16.row.col.f32.bf16.bf16.f32 "
        "{%0,%1,%2,%3},{%4,%5,%6,%7},{%8,%9},{%0,%1,%2,%3};"
        : "+f"(d[0]), "+f"(d[1]), "+f"(d[2]), "+f"(d[3])
        : "r"(a[0]), "r"(a[1]), "r"(a[2]), "r"(a[3]), "r"(b[0]), "r"(b[1]));
}

// smem plane layout: 16B chunks; chunk(s, r) at ((s<<7) + (r ^ (s<<1)))*16.
//  - cp.async store side: threads (r, s=0..3) hit distinct bank groups.
//  - ldmatrix read side: 8 consecutive rows, fixed s -> 8 distinct bank groups.
__device__ __forceinline__ uint32_t chunk_off(int s, int r) {
    return (uint32_t)(((s << 7) + (r ^ (s << 1))) << 4);
}

// ============================================================================
// fp32 -> bf16 hi/lo split (elementwise)
// ============================================================================
__global__ __launch_bounds__(256)
void split_bf16(const float* __restrict__ s, __nv_bfloat16* __restrict__ hi,
                __nv_bfloat16* __restrict__ lo, size_t n4) {
    size_t i = (size_t)blockIdx.x * blockDim.x + threadIdx.x;
    size_t stride = (size_t)gridDim.x * blockDim.x;
    for (; i < n4; i += stride) {
        float4 v = reinterpret_cast<const float4*>(s)[i];
        __nv_bfloat16 h0 = __float2bfloat16_rn(v.x), h1 = __float2bfloat16_rn(v.y);
        __nv_bfloat16 h2 = __float2bfloat16_rn(v.z), h3 = __float2bfloat16_rn(v.w);
        __nv_bfloat16 l0 = __float2bfloat16_rn(v.x - __bfloat162float(h0));
        __nv_bfloat16 l1 = __float2bfloat16_rn(v.y - __bfloat162float(h1));
        __nv_bfloat16 l2 = __float2bfloat16_rn(v.z - __bfloat162float(h2));
        __nv_bfloat16 l3 = __float2bfloat16_rn(v.w - __bfloat162float(h3));
        reinterpret_cast<__nv_bfloat162*>(hi)[2 * i]     = __halves2bfloat162(h0, h1);
        reinterpret_cast<__nv_bfloat162*>(hi)[2 * i + 1] = __halves2bfloat162(h2, h3);
        reinterpret_cast<__nv_bfloat162*>(lo)[2 * i]     = __halves2bfloat162(l0, l1);
        reinterpret_cast<__nv_bfloat162*>(lo)[2 * i + 1] = __halves2bfloat162(l2, l3);
    }
}

// ============================================================================
// HMMA bf16 GEMM (3-product split ~ fp32 accuracy):
//   C[M,Nc] = A[M,K] * B[Nc,K]^T (+ bias)
// CTA 128x128, BK=32 bf16, 256 threads (8 warps, warp tile 64x32),
// 3-stage cp.async pipeline, ldmatrix fragment loads.
// Requires Nc % 128 == 0, K % 32 == 0.
// ============================================================================
#define BKi     32
#define PLANE_B 8192                 // 128 rows * 32 bf16 * 2B
#define STAGE_B (4 * PLANE_B)        // Ahi, Alo, Bhi, Blo = 32 KB
#define NSTAGE  3
#define GSMEM   (NSTAGE * STAGE_B + 256)

template <bool BIAS>
__global__ __launch_bounds__(256, 1)
void gemm_hmma(const __nv_bfloat16* __restrict__ Ahi, const __nv_bfloat16* __restrict__ Alo,
               const __nv_bfloat16* __restrict__ Bhi, const __nv_bfloat16* __restrict__ Blo,
               const float* __restrict__ bias, float* __restrict__ C,
               int M, int Nc, int K) {
    extern __shared__ char dsm[];
    const uint32_t base = s2u(dsm);

    const int tid  = threadIdx.x;
    const int warp = tid >> 5, lane = tid & 31;
    const int row0 = blockIdx.y * 128, col0 = blockIdx.x * 128;
    const int wm = (warp >> 2) * 64;      // 0 / 64
    const int wn = (warp & 3) * 32;       // 0 / 32 / 64 / 96
    const int nk = K / BKi;

    float acc[4][4][4];
    #pragma unroll
    for (int i = 0; i < 4; ++i)
        #pragma unroll
        for (int j = 0; j < 4; ++j)
            #pragma unroll
            for (int c = 0; c < 4; ++c) acc[i][j][c] = 0.f;

    // stage one BK chunk (4 planes x 512 chunks = 2048 chunks, 8 per thread)
    auto stage = [&](int t, int sb) {
        const int k0 = t * BKi;
        const uint32_t sbase = base + sb * STAGE_B;
        #pragma unroll
        for (int l = 0; l < 8; ++l) {
            int idx = tid + l * 256;          // 0..2047
            int p   = idx >> 9;               // plane
            int cid = idx & 511;
            int r   = cid >> 2;               // tile row
            int s   = cid & 3;                // 8-elem k slab
            const __nv_bfloat16* pl = (p == 0) ? Ahi : (p == 1) ? Alo
                                    : (p == 2) ? Bhi : Blo;
            uint32_t dst = sbase + p * PLANE_B + chunk_off(s, r);
            if (p < 2) {
                int gr = row0 + r;
                int ok = (gr < M);
                cp16p(dst, pl + (size_t)(ok ? gr : 0) * K + k0 + s * 8, ok ? 16 : 0);
            } else {
                cp16(dst, pl + (size_t)(col0 + r) * K + k0 + s * 8);
            }
        }
    };

    stage(0, 0); CPCOMMIT();
    stage(1, 1); CPCOMMIT();
    stage(2, 2); CPCOMMIT();

    const int a_r = lane & 15, a_s = lane >> 4;        // ldmatrix x4 lane map
    const int b_r = lane & 7,  b_s = (lane >> 3) & 1;  // ldmatrix x2 lane map

    for (int t = 0; t < nk; ++t) {
        const int sb = t % NSTAGE;
        cpwait(min(nk - 1 - t, 2));
        __syncthreads();

        const uint32_t pb = base + sb * STAGE_B;
        #pragma unroll
        for (int ks = 0; ks < 2; ++ks) {
            uint32_t ah[4][4], al[4][4], bh[4][2], bl[4][2];
            #pragma unroll
            for (int ni = 0; ni < 4; ++ni) {
                uint32_t off = chunk_off(2 * ks + b_s, wn + ni * 8 + b_r);
                ldm2(bh[ni], pb + 2 * PLANE_B + off);
                ldm2(bl[ni], pb + 3 * PLANE_B + off);
            }
            #pragma unroll
            for (int mi = 0; mi < 4; ++mi) {
                uint32_t off = chunk_off(2 * ks + a_s, wm + mi * 16 + a_r);
                ldm4(ah[mi], pb + off);
                ldm4(al[mi], pb + PLANE_B + off);
            }
            #pragma unroll
            for (int mi = 0; mi < 4; ++mi)
                #pragma unroll
                for (int ni = 0; ni < 4; ++ni) {
                    mma16816(acc[mi][ni], ah[mi], bh[ni]);
                    mma16816(acc[mi][ni], ah[mi], bl[ni]);
                    mma16816(acc[mi][ni], al[mi], bh[ni]);
                }
        }
        __syncthreads();
        if (t + NSTAGE < nk) { stage(t + NSTAGE, sb); CPCOMMIT(); }
    }

    // epilogue: direct float2 stores
    const int er = lane >> 2, ec = 2 * (lane & 3);
    #pragma unroll
    for (int mi = 0; mi < 4; ++mi) {
        #pragma unroll
        for (int ni = 0; ni < 4; ++ni) {
            int gc = col0 + wn + ni * 8 + ec;
            float b0 = 0.f, b1 = 0.f;
            if (BIAS) { b0 = bias[gc]; b1 = bias[gc + 1]; }
            int gr0 = row0 + wm + mi * 16 + er;
            if (gr0 < M) {
                float2 v = make_float2(acc[mi][ni][0] + b0, acc[mi][ni][1] + b1);
                *reinterpret_cast<float2*>(&C[(size_t)gr0 * Nc + gc]) = v;
            }
            if (gr0 + 8 < M) {
                float2 v = make_float2(acc[mi][ni][2] + b0, acc[mi][ni][3] + b1);
                *reinterpret_cast<float2*>(&C[(size_t)(gr0 + 8) * Nc + gc]) = v;
            }
        }
    }
}

// ============================================================================
// RoPE (skip CLS token 0) + performer feature map.
// ============================================================================
__global__ __launch_bounds__(128)
void rope_feat(const float* __restrict__ qkv, const float* __restrict__ proj,
               const float* __restrict__ fcos, const float* __restrict__ fsin,
               float* __restrict__ qf, float* __restrict__ kf) {
    const int n = blockIdx.x, h = blockIdx.y, b = blockIdx.z;
    const int tid  = threadIdx.x;
    const int half = tid >> 6;
    const int lane = tid & 63;
    __shared__ float raw[2][Dv];
    __shared__ float vec[2][Dv];
    const float scale = 0.35355339059327379f;  // 64^-0.25

    size_t basei = ((size_t)(b * Nv + n) * 3 + half) * (Hv * Dv) + h * Dv + lane;
    raw[half][lane] = qkv[basei];
    __syncthreads();

    float val;
    if (n == 0) {
        val = raw[half][lane];
    } else {
        int i  = lane >> 1;
        float c = fcos[(size_t)(n - 1) * (Dv / 2) + i];
        float s = fsin[(size_t)(n - 1) * (Dv / 2) + i];
        float ev = raw[half][lane & ~1];
        float od = raw[half][lane |  1];
        val = (lane & 1) ? (ev * s + od * c) : (ev * c - od * s);
    }
    vec[half][lane] = val * scale;
    __syncthreads();

    float accv = 0.f;
    const float* pr = proj + (size_t)lane * Dv;
    #pragma unroll 8
    for (int d = 0; d < Dv; ++d) accv += vec[half][d] * pr[d];
    accv = fmaxf(accv, 0.f) + 1e-6f;

    size_t o = (((size_t)b * Hv + h) * Nv + n) * Dv + lane;
    (half == 0 ? qf : kf)[o] = accv;
}

// ============================================================================
// context + k_sum (8-way n-split, atomic accumulate)
// ============================================================================
#define CSPLIT 8
__global__ __launch_bounds__(256)
void ctx_kernel(const float* __restrict__ kf, const float* __restrict__ qkv,
                float* __restrict__ ctx, float* __restrict__ ksum) {
    constexpr int TILE = 8;
    __shared__ float ks[TILE][Dv];
    __shared__ float vs[TILE][Dv];

    const int bh = blockIdx.x;
    const int b = bh / Hv, h = bh % Hv;
    const int tid = threadIdx.x;
    const int tx = tid & 15;
    const int ty = tid >> 4;

    const int chunk  = (Nv + CSPLIT - 1) / CSPLIT;
    const int nstart = blockIdx.y * chunk;
    const int nend   = min(nstart + chunk, Nv);

    const int which = tid >> 7;
    const int rr    = (tid >> 4) & 7;
    const int c4    = (tid & 15) * 4;

    float acc[4][4] = {};
    float ksl = 0.f;

    for (int n0 = nstart; n0 < nend; n0 += TILE) {
        int n = n0 + rr;
        float4 v;
        if (n < nend) {
            if (which == 0)
                v = *reinterpret_cast<const float4*>(
                        &kf[(((size_t)b * Hv + h) * Nv + n) * Dv + c4]);
            else
                v = *reinterpret_cast<const float4*>(
                        &qkv[(((size_t)(b * Nv + n)) * 3 + 2) * (Hv * Dv) + h * Dv + c4]);
        } else {
            v = make_float4(0.f, 0.f, 0.f, 0.f);
        }
        __syncthreads();
        float* dst = (which == 0) ? &ks[rr][c4] : &vs[rr][c4];
        dst[0] = v.x; dst[1] = v.y; dst[2] = v.z; dst[3] = v.w;
        __syncthreads();

        #pragma unroll
        for (int r = 0; r < TILE; ++r) {
            float a[4], bb[4];
            #pragma unroll
            for (int i = 0; i < 4; ++i) a[i]  = ks[r][ty * 4 + i];
            #pragma unroll
            for (int j = 0; j < 4; ++j) bb[j] = vs[r][tx * 4 + j];
            #pragma unroll
            for (int i = 0; i < 4; ++i)
                #pragma unroll
                for (int j = 0; j < 4; ++j)
                    acc[i][j] += a[i] * bb[j];
        }
        if (tid < Dv) {
            #pragma unroll
            for (int r = 0; r < TILE; ++r) ksl += ks[r][tid];
        }
    }

    #pragma unroll
    for (int i = 0; i < 4; ++i)
        #pragma unroll
        for (int j = 0; j < 4; ++j)
            atomicAdd(&ctx[((size_t)bh * Dv + ty * 4 + i) * Dv + tx * 4 + j],
                      acc[i][j]);
    if (tid < Dv) atomicAdd(&ksum[(size_t)bh * Dv + tid], ksl);
}

// ============================================================================
// out = (ctx . qf) / (qf . ksum)  -> written directly as bf16 hi/lo planes
// ============================================================================
#define NCHUNK 8
__global__ __launch_bounds__(256)
void out_kernel(const float* __restrict__ qf, const float* __restrict__ ctx,
                const float* __restrict__ ksum,
                __nv_bfloat16* __restrict__ ahi, __nv_bfloat16* __restrict__ alo) {
    __shared__ float sctx[Dv][Dv];
    __shared__ float sks[Dv];
    __shared__ float sqf[4][Dv];

    const int bh = blockIdx.x;
    const int b = bh / Hv, h = bh % Hv;
    const int tid = threadIdx.x;
    const int g = tid >> 6, e = tid & 63;

    for (int l = tid; l < Dv * Dv / 4; l += 256) {
        float4 v = reinterpret_cast<const float4*>(ctx + (size_t)bh * Dv * Dv)[l];
        reinterpret_cast<float4*>(&sctx[0][0])[l] = v;
    }
    if (tid < Dv) sks[tid] = ksum[(size_t)bh * Dv + tid];
    __syncthreads();

    const int chunk  = (Nv + NCHUNK - 1) / NCHUNK;
    const int nstart = blockIdx.y * chunk;
    const int nend   = min(nstart + chunk, Nv);

    for (int n0 = nstart; n0 < nend; n0 += 4) {
        int n = n0 + g;
        __syncthreads();
        if (n < nend) sqf[g][e] = qf[(((size_t)b * Hv + h) * Nv + n) * Dv + e];
        __syncthreads();
        if (n < nend) {
            float denom = 0.f, accv = 0.f;
            #pragma unroll 8
            for (int d = 0; d < Dv; ++d) {
                float q = sqf[g][d];
                denom += q * sks[d];
                accv  += q * sctx[d][e];
            }
            float val = accv / denom;
            __nv_bfloat16 hv = __float2bfloat16_rn(val);
            __nv_bfloat16 lv = __float2bfloat16_rn(val - __bfloat162float(hv));
            size_t o = ((size_t)(b * Nv + n)) * DIMv + h * Dv + e;
            ahi[o] = hv;
            alo[o] = lv;
        }
    }
}

// ============================================================================
// launcher
// ============================================================================
extern "C" void kernel_launch(void* const* d_in, const int* in_sizes, int n_in,
                              void* d_out, int out_size) {
    const float* x     = (const float*)d_in[0];
    const float* W_qkv = (const float*)d_in[1];
    const float* W_out = (const float*)d_in[2];
    const float* b_out = (const float*)d_in[3];
    const float* proj  = (const float*)d_in[4];
    const float* fcos  = (const float*)d_in[5];
    const float* fsin  = (const float*)d_in[6];
    float* out = (float*)d_out;

    float *p_qkv, *p_qf, *p_kf, *p_ctx, *p_ksum;
    cudaGetSymbolAddress((void**)&p_qkv,  g_qkv);
    cudaGetSymbolAddress((void**)&p_qf,   g_qf);
    cudaGetSymbolAddress((void**)&p_kf,   g_kf);
    cudaGetSymbolAddress((void**)&p_ctx,  g_ctx);
    cudaGetSymbolAddress((void**)&p_ksum, g_ksum);

    __nv_bfloat16 *xhi, *xlo, *wqhi, *wqlo, *wohi, *wolo, *ahi, *alo;
    cudaGetSymbolAddress((void**)&xhi,  g_xhi);  cudaGetSymbolAddress((void**)&xlo,  g_xlo);
    cudaGetSymbolAddress((void**)&wqhi, g_wqhi); cudaGetSymbolAddress((void**)&wqlo, g_wqlo);
    cudaGetSymbolAddress((void**)&wohi, g_wohi); cudaGetSymbolAddress((void**)&wolo, g_wolo);
    cudaGetSymbolAddress((void**)&ahi,  g_ahi);  cudaGetSymbolAddress((void**)&alo,  g_alo);

    cudaFuncSetAttribute(gemm_hmma<false>,
                         cudaFuncAttributeMaxDynamicSharedMemorySize, GSMEM);
    cudaFuncSetAttribute(gemm_hmma<true>,
                         cudaFuncAttributeMaxDynamicSharedMemorySize, GSMEM);

    // 0) split fp32 -> bf16 hi/lo
    split_bf16<<<2048, 256>>>(x,     xhi,  xlo,  (size_t)M1 * DIMv / 4);
    split_bf16<<<512,  256>>>(W_qkv, wqhi, wqlo, (size_t)G3 * DIMv / 4);
    split_bf16<<<256,  256>>>(W_out, wohi, wolo, (size_t)DIMv * DIMv / 4);

    // 1) QKV projection (bf16 HMMA, 3-product split)
    {
        dim3 grid(G3 / 128, (M1 + 127) / 128);
        gemm_hmma<false><<<grid, 256, GSMEM>>>(xhi, xlo, wqhi, wqlo, nullptr,
                                               p_qkv, M1, G3, DIMv);
    }
    // 2) RoPE + feature map
    {
        dim3 grid(Nv, Hv, Bv);
        rope_feat<<<grid, 128>>>(p_qkv, proj, fcos, fsin, p_qf, p_kf);
    }
    // 3) context + k_sum
    cudaMemsetAsync(p_ctx,  0, (size_t)Bv * Hv * Dv * Dv * sizeof(float));
    cudaMemsetAsync(p_ksum, 0, (size_t)Bv * Hv * Dv * sizeof(float));
    {
        dim3 grid(Bv * Hv, CSPLIT);
        ctx_kernel<<<grid, 256>>>(p_kf, p_qkv, p_ctx, p_ksum);
    }
    // 4) per-token output contraction (emits bf16 hi/lo directly)
    {
        dim3 grid(Bv * Hv, NCHUNK);
        out_kernel<<<grid, 256>>>(p_qf, p_ctx, p_ksum, ahi, alo);
    }
    // 5) output projection + bias (bf16 HMMA, 3-product split)
    {
        dim3 grid(DIMv / 128, (M1 + 127) / 128);
        gemm_hmma<true><<<grid, 256, GSMEM>>>(ahi, alo, wohi, wolo, b_out,
                                              out, M1, DIMv, DIMv);
    }
}

// round 6
// speedup vs baseline: 1.2356x; 1.1048x over previous
#include <cuda_runtime.h>
#include <cuda_fp16.h>
#include <cstdint>
#include <cstddef>

// Problem constants
#define Bv   32
#define Nv   1025
#define DIMv 768
#define Hv   12
#define Dv   64
#define M1   (Bv * Nv)          // 32800 tokens
#define G3   (3 * Hv * Dv)      // 2304

// -------- scratch (device globals; no allocation allowed) --------
__device__ float g_qkv [(size_t)M1 * G3];
__device__ float g_qf  [(size_t)Bv * Hv * Nv * Dv];
__device__ float g_kf  [(size_t)Bv * Hv * Nv * Dv];
__device__ float g_ctx [(size_t)Bv * Hv * Dv * Dv];
__device__ float g_ksum[(size_t)Bv * Hv * Dv];
// fp16 single planes
__device__ __half g_xh [(size_t)M1 * DIMv];
__device__ __half g_wqh[(size_t)G3 * DIMv];
__device__ __half g_woh[(size_t)DIMv * DIMv];
__device__ __half g_ah [(size_t)M1 * DIMv];

// ============================================================================
// helpers (baseline PTX only: cp.async + ldmatrix + mma.sync)
// ============================================================================
__device__ __forceinline__ uint32_t s2u(const void* p) {
    uint32_t a;
    asm("{ .reg .u64 t; cvta.to.shared.u64 t, %1; cvt.u32.u64 %0, t; }"
        : "=r"(a) : "l"(p));
    return a;
}
__device__ __forceinline__ void cp16(uint32_t dst, const void* src) {
    asm volatile("cp.async.cg.shared.global [%0], [%1], 16;"
                 :: "r"(dst), "l"(src) : "memory");
}
__device__ __forceinline__ void cp16p(uint32_t dst, const void* src, int p) {
    asm volatile("cp.async.cg.shared.global [%0], [%1], 16, %2;"
                 :: "r"(dst), "l"(src), "r"(p) : "memory");
}
#define CPCOMMIT() asm volatile("cp.async.commit_group;" ::: "memory")
__device__ __forceinline__ void cpwait(int n) {
    if (n >= 2)      asm volatile("cp.async.wait_group 2;" ::: "memory");
    else if (n == 1) asm volatile("cp.async.wait_group 1;" ::: "memory");
    else             asm volatile("cp.async.wait_group 0;" ::: "memory");
}
__device__ __forceinline__ void ldm4(uint32_t* r, uint32_t a) {
    asm volatile("ldmatrix.sync.aligned.m8n8.x4.shared.b16 {%0,%1,%2,%3}, [%4];"
                 : "=r"(r[0]), "=r"(r[1]), "=r"(r[2]), "=r"(r[3]) : "r"(a));
}
__device__ __forceinline__ void ldm2(uint32_t* r, uint32_t a) {
    asm volatile("ldmatrix.sync.aligned.m8n8.x2.shared.b16 {%0,%1}, [%2];"
                 : "=r"(r[0]), "=r"(r[1]) : "r"(a));
}
__device__ __forceinline__ void mma16816(float* d, const uint32_t* a,
                                         const uint32_t* b) {
    asm volatile(
        "mma.sync.aligned.m16n8k16.row.col.f32.f16.f16.f32 "
        "{%0,%1,%2,%3},{%4,%5,%6,%7},{%8,%9},{%0,%1,%2,%3};"
        : "+f"(d[0]), "+f"(d[1]), "+f"(d[2]), "+f"(d[3])
        : "r"(a[0]), "r"(a[1]), "r"(a[2]), "r"(a[3]), "r"(b[0]), "r"(b[1]));
}

// smem plane layout: 16B chunks; chunk(s, r) at ((s<<7) + (r ^ (s<<1)))*16.
// Conflict-free on both cp.async store side and ldmatrix read side (R5-proven).
__device__ __forceinline__ uint32_t chunk_off(int s, int r) {
    return (uint32_t)(((s << 7) + (r ^ (s << 1))) << 4);
}

// ============================================================================
// fp32 -> fp16 conversion (elementwise)
// ============================================================================
__global__ __launch_bounds__(256)
void conv_fp16(const float* __restrict__ s, __half* __restrict__ h, size_t n4) {
    size_t i = (size_t)blockIdx.x * blockDim.x + threadIdx.x;
    size_t stride = (size_t)gridDim.x * blockDim.x;
    for (; i < n4; i += stride) {
        float4 v = reinterpret_cast<const float4*>(s)[i];
        __half2 a = __floats2half2_rn(v.x, v.y);
        __half2 b = __floats2half2_rn(v.z, v.w);
        reinterpret_cast<__half2*>(h)[2 * i]     = a;
        reinterpret_cast<__half2*>(h)[2 * i + 1] = b;
    }
}

// ============================================================================
// HMMA fp16 single-pass GEMM:  C[M,Nc] = A[M,K] * B[Nc,K]^T (+ bias)
// CTA 128x128, BK=32 fp16, 256 threads (8 warps, warp tile 64x32),
// 4-stage cp.async pipeline (16 KB/stage), ldmatrix fragment loads.
// Requires Nc % 128 == 0, K % 32 == 0.
// ============================================================================
#define BKi     32
#define PLANE_B 8192                 // 128 rows * 32 fp16 * 2B
#define STAGE_B (2 * PLANE_B)        // A, B = 16 KB
#define NSTAGE  4
#define GSMEM   (NSTAGE * STAGE_B)

template <bool BIAS>
__global__ __launch_bounds__(256, 2)
void gemm_hmma(const __half* __restrict__ Ah, const __half* __restrict__ Bh,
               const float* __restrict__ bias, float* __restrict__ C,
               int M, int Nc, int K) {
    extern __shared__ char dsm[];
    const uint32_t base = s2u(dsm);

    const int tid  = threadIdx.x;
    const int warp = tid >> 5, lane = tid & 31;
    const int row0 = blockIdx.y * 128, col0 = blockIdx.x * 128;
    const int wm = (warp >> 2) * 64;      // 0 / 64
    const int wn = (warp & 3) * 32;       // 0 / 32 / 64 / 96
    const int nk = K / BKi;

    float acc[4][4][4];
    #pragma unroll
    for (int i = 0; i < 4; ++i)
        #pragma unroll
        for (int j = 0; j < 4; ++j)
            #pragma unroll
            for (int c = 0; c < 4; ++c) acc[i][j][c] = 0.f;

    // stage one BK chunk: 2 planes x 512 chunks = 1024 cp.async, 4 per thread
    auto stage = [&](int t, int sb) {
        const int k0 = t * BKi;
        const uint32_t sbase = base + sb * STAGE_B;
        #pragma unroll
        for (int l = 0; l < 4; ++l) {
            int idx = tid + l * 256;          // 0..1023
            int p   = idx >> 9;               // plane: 0=A, 1=B
            int cid = idx & 511;
            int r   = cid >> 2;               // tile row
            int s   = cid & 3;                // 8-elem k slab
            uint32_t dst = sbase + p * PLANE_B + chunk_off(s, r);
            if (p == 0) {
                int gr = row0 + r;
                int ok = (gr < M);
                cp16p(dst, Ah + (size_t)(ok ? gr : 0) * K + k0 + s * 8, ok ? 16 : 0);
            } else {
                cp16(dst, Bh + (size_t)(col0 + r) * K + k0 + s * 8);
            }
        }
    };

    stage(0, 0); CPCOMMIT();
    stage(1, 1); CPCOMMIT();
    stage(2, 2); CPCOMMIT();

    const int a_r = lane & 15, a_s = lane >> 4;        // ldmatrix x4 lane map
    const int b_r = lane & 7,  b_s = (lane >> 3) & 1;  // ldmatrix x2 lane map

    for (int t = 0; t < nk; ++t) {
        const int sb = t % NSTAGE;
        cpwait(min(nk - 1 - t, 2));
        __syncthreads();

        const uint32_t pb = base + sb * STAGE_B;
        #pragma unroll
        for (int ks = 0; ks < 2; ++ks) {
            uint32_t af[4][4], bf[4][2];
            #pragma unroll
            for (int ni = 0; ni < 4; ++ni)
                ldm2(bf[ni], pb + PLANE_B + chunk_off(2 * ks + b_s, wn + ni * 8 + b_r));
            #pragma unroll
            for (int mi = 0; mi < 4; ++mi)
                ldm4(af[mi], pb + chunk_off(2 * ks + a_s, wm + mi * 16 + a_r));
            #pragma unroll
            for (int mi = 0; mi < 4; ++mi)
                #pragma unroll
                for (int ni = 0; ni < 4; ++ni)
                    mma16816(acc[mi][ni], af[mi], bf[ni]);
        }
        __syncthreads();
        if (t + NSTAGE - 1 < nk) { stage(t + NSTAGE - 1, (t + NSTAGE - 1) % NSTAGE); CPCOMMIT(); }
    }

    // epilogue: direct float2 stores
    const int er = lane >> 2, ec = 2 * (lane & 3);
    #pragma unroll
    for (int mi = 0; mi < 4; ++mi) {
        #pragma unroll
        for (int ni = 0; ni < 4; ++ni) {
            int gc = col0 + wn + ni * 8 + ec;
            float b0 = 0.f, b1 = 0.f;
            if (BIAS) { b0 = bias[gc]; b1 = bias[gc + 1]; }
            int gr0 = row0 + wm + mi * 16 + er;
            if (gr0 < M) {
                float2 v = make_float2(acc[mi][ni][0] + b0, acc[mi][ni][1] + b1);
                *reinterpret_cast<float2*>(&C[(size_t)gr0 * Nc + gc]) = v;
            }
            if (gr0 + 8 < M) {
                float2 v = make_float2(acc[mi][ni][2] + b0, acc[mi][ni][3] + b1);
                *reinterpret_cast<float2*>(&C[(size_t)(gr0 + 8) * Nc + gc]) = v;
            }
        }
    }
}

// ============================================================================
// RoPE (skip CLS token 0) + performer feature map.
// ============================================================================
__global__ __launch_bounds__(128)
void rope_feat(const float* __restrict__ qkv, const float* __restrict__ proj,
               const float* __restrict__ fcos, const float* __restrict__ fsin,
               float* __restrict__ qf, float* __restrict__ kf) {
    const int n = blockIdx.x, h = blockIdx.y, b = blockIdx.z;
    const int tid  = threadIdx.x;
    const int half = tid >> 6;
    const int lane = tid & 63;
    __shared__ float raw[2][Dv];
    __shared__ float vec[2][Dv];
    const float scale = 0.35355339059327379f;  // 64^-0.25

    size_t basei = ((size_t)(b * Nv + n) * 3 + half) * (Hv * Dv) + h * Dv + lane;
    raw[half][lane] = qkv[basei];
    __syncthreads();

    float val;
    if (n == 0) {
        val = raw[half][lane];
    } else {
        int i  = lane >> 1;
        float c = fcos[(size_t)(n - 1) * (Dv / 2) + i];
        float s = fsin[(size_t)(n - 1) * (Dv / 2) + i];
        float ev = raw[half][lane & ~1];
        float od = raw[half][lane |  1];
        val = (lane & 1) ? (ev * s + od * c) : (ev * c - od * s);
    }
    vec[half][lane] = val * scale;
    __syncthreads();

    float accv = 0.f;
    const float* pr = proj + (size_t)lane * Dv;
    #pragma unroll 8
    for (int d = 0; d < Dv; ++d) accv += vec[half][d] * pr[d];
    accv = fmaxf(accv, 0.f) + 1e-6f;

    size_t o = (((size_t)b * Hv + h) * Nv + n) * Dv + lane;
    (half == 0 ? qf : kf)[o] = accv;
}

// ============================================================================
// context + k_sum (8-way n-split, atomic accumulate)
// ============================================================================
#define CSPLIT 8
__global__ __launch_bounds__(256)
void ctx_kernel(const float* __restrict__ kf, const float* __restrict__ qkv,
                float* __restrict__ ctx, float* __restrict__ ksum) {
    constexpr int TILE = 8;
    __shared__ float ks[TILE][Dv];
    __shared__ float vs[TILE][Dv];

    const int bh = blockIdx.x;
    const int b = bh / Hv, h = bh % Hv;
    const int tid = threadIdx.x;
    const int tx = tid & 15;
    const int ty = tid >> 4;

    const int chunk  = (Nv + CSPLIT - 1) / CSPLIT;
    const int nstart = blockIdx.y * chunk;
    const int nend   = min(nstart + chunk, Nv);

    const int which = tid >> 7;
    const int rr    = (tid >> 4) & 7;
    const int c4    = (tid & 15) * 4;

    float acc[4][4] = {};
    float ksl = 0.f;

    for (int n0 = nstart; n0 < nend; n0 += TILE) {
        int n = n0 + rr;
        float4 v;
        if (n < nend) {
            if (which == 0)
                v = *reinterpret_cast<const float4*>(
                        &kf[(((size_t)b * Hv + h) * Nv + n) * Dv + c4]);
            else
                v = *reinterpret_cast<const float4*>(
                        &qkv[(((size_t)(b * Nv + n)) * 3 + 2) * (Hv * Dv) + h * Dv + c4]);
        } else {
            v = make_float4(0.f, 0.f, 0.f, 0.f);
        }
        __syncthreads();
        float* dst = (which == 0) ? &ks[rr][c4] : &vs[rr][c4];
        dst[0] = v.x; dst[1] = v.y; dst[2] = v.z; dst[3] = v.w;
        __syncthreads();

        #pragma unroll
        for (int r = 0; r < TILE; ++r) {
            float a[4], bb[4];
            #pragma unroll
            for (int i = 0; i < 4; ++i) a[i]  = ks[r][ty * 4 + i];
            #pragma unroll
            for (int j = 0; j < 4; ++j) bb[j] = vs[r][tx * 4 + j];
            #pragma unroll
            for (int i = 0; i < 4; ++i)
                #pragma unroll
                for (int j = 0; j < 4; ++j)
                    acc[i][j] += a[i] * bb[j];
        }
        if (tid < Dv) {
            #pragma unroll
            for (int r = 0; r < TILE; ++r) ksl += ks[r][tid];
        }
    }

    #pragma unroll
    for (int i = 0; i < 4; ++i)
        #pragma unroll
        for (int j = 0; j < 4; ++j)
            atomicAdd(&ctx[((size_t)bh * Dv + ty * 4 + i) * Dv + tx * 4 + j],
                      acc[i][j]);
    if (tid < Dv) atomicAdd(&ksum[(size_t)bh * Dv + tid], ksl);
}

// ============================================================================
// out = (ctx . qf) / (qf . ksum)  -> written directly as fp16
// ============================================================================
#define NCHUNK 8
__global__ __launch_bounds__(256)
void out_kernel(const float* __restrict__ qf, const float* __restrict__ ctx,
                const float* __restrict__ ksum, __half* __restrict__ ah) {
    __shared__ float sctx[Dv][Dv];
    __shared__ float sks[Dv];
    __shared__ float sqf[4][Dv];

    const int bh = blockIdx.x;
    const int b = bh / Hv, h = bh % Hv;
    const int tid = threadIdx.x;
    const int g = tid >> 6, e = tid & 63;

    for (int l = tid; l < Dv * Dv / 4; l += 256) {
        float4 v = reinterpret_cast<const float4*>(ctx + (size_t)bh * Dv * Dv)[l];
        reinterpret_cast<float4*>(&sctx[0][0])[l] = v;
    }
    if (tid < Dv) sks[tid] = ksum[(size_t)bh * Dv + tid];
    __syncthreads();

    const int chunk  = (Nv + NCHUNK - 1) / NCHUNK;
    const int nstart = blockIdx.y * chunk;
    const int nend   = min(nstart + chunk, Nv);

    for (int n0 = nstart; n0 < nend; n0 += 4) {
        int n = n0 + g;
        __syncthreads();
        if (n < nend) sqf[g][e] = qf[(((size_t)b * Hv + h) * Nv + n) * Dv + e];
        __syncthreads();
        if (n < nend) {
            float denom = 0.f, accv = 0.f;
            #pragma unroll 8
            for (int d = 0; d < Dv; ++d) {
                float q = sqf[g][d];
                denom += q * sks[d];
                accv  += q * sctx[d][e];
            }
            ah[((size_t)(b * Nv + n)) * DIMv + h * Dv + e] =
                __float2half_rn(accv / denom);
        }
    }
}

// ============================================================================
// launcher
// ============================================================================
extern "C" void kernel_launch(void* const* d_in, const int* in_sizes, int n_in,
                              void* d_out, int out_size) {
    const float* x     = (const float*)d_in[0];
    const float* W_qkv = (const float*)d_in[1];
    const float* W_out = (const float*)d_in[2];
    const float* b_out = (const float*)d_in[3];
    const float* proj  = (const float*)d_in[4];
    const float* fcos  = (const float*)d_in[5];
    const float* fsin  = (const float*)d_in[6];
    float* out = (float*)d_out;

    float *p_qkv, *p_qf, *p_kf, *p_ctx, *p_ksum;
    cudaGetSymbolAddress((void**)&p_qkv,  g_qkv);
    cudaGetSymbolAddress((void**)&p_qf,   g_qf);
    cudaGetSymbolAddress((void**)&p_kf,   g_kf);
    cudaGetSymbolAddress((void**)&p_ctx,  g_ctx);
    cudaGetSymbolAddress((void**)&p_ksum, g_ksum);

    __half *xh, *wqh, *woh, *ah;
    cudaGetSymbolAddress((void**)&xh,  g_xh);
    cudaGetSymbolAddress((void**)&wqh, g_wqh);
    cudaGetSymbolAddress((void**)&woh, g_woh);
    cudaGetSymbolAddress((void**)&ah,  g_ah);

    cudaFuncSetAttribute(gemm_hmma<false>,
                         cudaFuncAttributeMaxDynamicSharedMemorySize, GSMEM);
    cudaFuncSetAttribute(gemm_hmma<true>,
                         cudaFuncAttributeMaxDynamicSharedMemorySize, GSMEM);

    // 0) fp32 -> fp16
    conv_fp16<<<2048, 256>>>(x,     xh,  (size_t)M1 * DIMv / 4);
    conv_fp16<<<512,  256>>>(W_qkv, wqh, (size_t)G3 * DIMv / 4);
    conv_fp16<<<256,  256>>>(W_out, woh, (size_t)DIMv * DIMv / 4);

    // 1) QKV projection (fp16 HMMA single-pass)
    {
        dim3 grid(G3 / 128, (M1 + 127) / 128);
        gemm_hmma<false><<<grid, 256, GSMEM>>>(xh, wqh, nullptr, p_qkv,
                                               M1, G3, DIMv);
    }
    // 2) RoPE + feature map
    {
        dim3 grid(Nv, Hv, Bv);
        rope_feat<<<grid, 128>>>(p_qkv, proj, fcos, fsin, p_qf, p_kf);
    }
    // 3) context + k_sum
    cudaMemsetAsync(p_ctx,  0, (size_t)Bv * Hv * Dv * Dv * sizeof(float));
    cudaMemsetAsync(p_ksum, 0, (size_t)Bv * Hv * Dv * sizeof(float));
    {
        dim3 grid(Bv * Hv, CSPLIT);
        ctx_kernel<<<grid, 256>>>(p_kf, p_qkv, p_ctx, p_ksum);
    }
    // 4) per-token output contraction (emits fp16 directly)
    {
        dim3 grid(Bv * Hv, NCHUNK);
        out_kernel<<<grid, 256>>>(p_qf, p_ctx, p_ksum, ah);
    }
    // 5) output projection + bias (fp16 HMMA single-pass)
    {
        dim3 grid(DIMv / 128, (M1 + 127) / 128);
        gemm_hmma<true><<<grid, 256, GSMEM>>>(ah, woh, b_out, out,
                                              M1, DIMv, DIMv);
    }
}

// round 7
// speedup vs baseline: 11.5034x; 9.3097x over previous
#include <cuda_runtime.h>
#include <cuda_fp16.h>
#include <cstdint>
#include <cstddef>

// Problem constants
#define Bv   32
#define Nv   1025
#define DIMv 768
#define Hv   12
#define Dv   64
#define M1   (Bv * Nv)          // 32800 tokens
#define G3   (3 * Hv * Dv)      // 2304
#define BH   (Bv * Hv)          // 384
#define NP   1056               // n padded to mult of 32 (K dim of ctx GEMM)

// -------- scratch (device globals; zero-initialized at load; pads of vt/kft/
//          ctxh are NEVER written and must stay zero — do not memset) --------
__device__ float  g_qkv [(size_t)M1 * G3];              // (b,n,3,h,d) fp32
__device__ __half g_xh  [(size_t)M1 * DIMv];
__device__ __half g_wqh [(size_t)G3 * DIMv];
__device__ __half g_woh [(size_t)DIMv * DIMv];
__device__ __half g_projh[(size_t)Dv * Dv];             // proj * 64^-0.25
__device__ __half g_qh  [(size_t)BH * Nv * Dv];         // roped q (bh,n,d)
__device__ __half g_kh  [(size_t)BH * Nv * Dv];         // roped k
__device__ __half g_vt  [(size_t)BH * 72 * NP];         // v^T (bh,d,n); row64=ones
__device__ __half g_qfh [(size_t)BH * Nv * Dv];         // feature(q) (bh,n,j)
__device__ __half g_kft [(size_t)BH * Dv * NP];         // feature(k)^T (bh,j,n)
__device__ __half g_ctxh[(size_t)BH * 128 * Dv];        // rows0-63 ctx[e][d], row64 ksum
__device__ __half g_ah  [(size_t)M1 * DIMv];            // attn out fp16 (token, h*d)

// ============================================================================
// PTX helpers (baseline PTX only: cp.async + ldmatrix + mma.sync)
// ============================================================================
__device__ __forceinline__ uint32_t s2u(const void* p) {
    uint32_t a;
    asm("{ .reg .u64 t; cvta.to.shared.u64 t, %1; cvt.u32.u64 %0, t; }"
        : "=r"(a) : "l"(p));
    return a;
}
__device__ __forceinline__ void cp16(uint32_t dst, const void* src) {
    asm volatile("cp.async.cg.shared.global [%0], [%1], 16;"
                 :: "r"(dst), "l"(src) : "memory");
}
__device__ __forceinline__ void cp16p(uint32_t dst, const void* src, int p) {
    asm volatile("cp.async.cg.shared.global [%0], [%1], 16, %2;"
                 :: "r"(dst), "l"(src), "r"(p) : "memory");
}
#define CPCOMMIT() asm volatile("cp.async.commit_group;" ::: "memory")
__device__ __forceinline__ void cpwait(int n) {
    if (n >= 2)      asm volatile("cp.async.wait_group 2;" ::: "memory");
    else if (n == 1) asm volatile("cp.async.wait_group 1;" ::: "memory");
    else             asm volatile("cp.async.wait_group 0;" ::: "memory");
}
__device__ __forceinline__ void ldm4(uint32_t* r, uint32_t a) {
    asm volatile("ldmatrix.sync.aligned.m8n8.x4.shared.b16 {%0,%1,%2,%3}, [%4];"
                 : "=r"(r[0]), "=r"(r[1]), "=r"(r[2]), "=r"(r[3]) : "r"(a));
}
__device__ __forceinline__ void ldm2(uint32_t* r, uint32_t a) {
    asm volatile("ldmatrix.sync.aligned.m8n8.x2.shared.b16 {%0,%1}, [%2];"
                 : "=r"(r[0]), "=r"(r[1]) : "r"(a));
}
__device__ __forceinline__ void mma16816(float* d, const uint32_t* a,
                                         const uint32_t* b) {
    asm volatile(
        "mma.sync.aligned.m16n8k16.row.col.f32.f16.f16.f32 "
        "{%0,%1,%2,%3},{%4,%5,%6,%7},{%8,%9},{%0,%1,%2,%3};"
        : "+f"(d[0]), "+f"(d[1]), "+f"(d[2]), "+f"(d[3])
        : "r"(a[0]), "r"(a[1]), "r"(a[2]), "r"(a[3]), "r"(b[0]), "r"(b[1]));
}

// 16B-chunk layouts: slab s, row r. Conflict-free for ldmatrix (R5/R6-proven
// pattern: bank group = (r ^ 2s) mod 8, distinct over 8 consecutive rows).
__device__ __forceinline__ uint32_t chunk_off(int s, int r) {      // 128-row plane
    return (uint32_t)(((s << 7) + (r ^ (s << 1))) << 4);
}
__device__ __forceinline__ uint32_t chunk_off64(int s, int r) {    // 64-row plane
    return (uint32_t)(((s << 6) + (r ^ (s << 1))) << 4);
}

// ============================================================================
// fp32 -> fp16 conversions
// ============================================================================
__global__ __launch_bounds__(256)
void conv_fp16(const float* __restrict__ s, __half* __restrict__ h, size_t n4) {
    size_t i = (size_t)blockIdx.x * blockDim.x + threadIdx.x;
    size_t stride = (size_t)gridDim.x * blockDim.x;
    for (; i < n4; i += stride) {
        float4 v = reinterpret_cast<const float4*>(s)[i];
        reinterpret_cast<__half2*>(h)[2 * i]     = __floats2half2_rn(v.x, v.y);
        reinterpret_cast<__half2*>(h)[2 * i + 1] = __floats2half2_rn(v.z, v.w);
    }
}
__global__ __launch_bounds__(256)
void conv_proj(const float* __restrict__ p, __half* __restrict__ ph) {
    int i = blockIdx.x * 256 + threadIdx.x;
    if (i < Dv * Dv) ph[i] = __float2half_rn(p[i] * 0.35355339059327379f);
}

// ============================================================================
// Main HMMA GEMM (unchanged from R6; 181 TF/s measured):
//   C[M,Nc] = A[M,K]*B[Nc,K]^T (+bias), CTA 128x128, BK=32, 4-stage cp.async
// ============================================================================
#define BKi     32
#define PLANE_B 8192
#define STAGE_B (2 * PLANE_B)
#define NSTAGE  4
#define GSMEM   (NSTAGE * STAGE_B)

template <bool BIAS>
__global__ __launch_bounds__(256, 2)
void gemm_hmma(const __half* __restrict__ Ah, const __half* __restrict__ Bh,
               const float* __restrict__ bias, float* __restrict__ C,
               int M, int Nc, int K) {
    extern __shared__ char dsm[];
    const uint32_t base = s2u(dsm);
    const int tid  = threadIdx.x;
    const int warp = tid >> 5, lane = tid & 31;
    const int row0 = blockIdx.y * 128, col0 = blockIdx.x * 128;
    const int wm = (warp >> 2) * 64, wn = (warp & 3) * 32;
    const int nk = K / BKi;

    float acc[4][4][4];
    #pragma unroll
    for (int i = 0; i < 4; ++i)
        #pragma unroll
        for (int j = 0; j < 4; ++j)
            #pragma unroll
            for (int c = 0; c < 4; ++c) acc[i][j][c] = 0.f;

    auto stage = [&](int t, int sb) {
        const int k0 = t * BKi;
        const uint32_t sbase = base + sb * STAGE_B;
        #pragma unroll
        for (int l = 0; l < 4; ++l) {
            int idx = tid + l * 256;
            int p = idx >> 9, cid = idx & 511;
            int r = cid >> 2, s = cid & 3;
            uint32_t dst = sbase + p * PLANE_B + chunk_off(s, r);
            if (p == 0) {
                int gr = row0 + r, ok = (gr < M);
                cp16p(dst, Ah + (size_t)(ok ? gr : 0) * K + k0 + s * 8, ok ? 16 : 0);
            } else {
                cp16(dst, Bh + (size_t)(col0 + r) * K + k0 + s * 8);
            }
        }
    };

    stage(0, 0); CPCOMMIT();
    stage(1, 1); CPCOMMIT();
    stage(2, 2); CPCOMMIT();

    const int a_r = lane & 15, a_s = lane >> 4;
    const int b_r = lane & 7,  b_s = (lane >> 3) & 1;

    for (int t = 0; t < nk; ++t) {
        const int sb = t % NSTAGE;
        cpwait(min(nk - 1 - t, 2));
        __syncthreads();
        const uint32_t pb = base + sb * STAGE_B;
        #pragma unroll
        for (int ks = 0; ks < 2; ++ks) {
            uint32_t af[4][4], bf[4][2];
            #pragma unroll
            for (int ni = 0; ni < 4; ++ni)
                ldm2(bf[ni], pb + PLANE_B + chunk_off(2 * ks + b_s, wn + ni * 8 + b_r));
            #pragma unroll
            for (int mi = 0; mi < 4; ++mi)
                ldm4(af[mi], pb + chunk_off(2 * ks + a_s, wm + mi * 16 + a_r));
            #pragma unroll
            for (int mi = 0; mi < 4; ++mi)
                #pragma unroll
                for (int ni = 0; ni < 4; ++ni)
                    mma16816(acc[mi][ni], af[mi], bf[ni]);
        }
        __syncthreads();
        if (t + NSTAGE - 1 < nk) { stage(t + NSTAGE - 1, (t + NSTAGE - 1) % NSTAGE); CPCOMMIT(); }
    }

    const int er = lane >> 2, ec = 2 * (lane & 3);
    #pragma unroll
    for (int mi = 0; mi < 4; ++mi)
        #pragma unroll
        for (int ni = 0; ni < 4; ++ni) {
            int gc = col0 + wn + ni * 8 + ec;
            float b0 = 0.f, b1 = 0.f;
            if (BIAS) { b0 = bias[gc]; b1 = bias[gc + 1]; }
            int gr0 = row0 + wm + mi * 16 + er;
            if (gr0 < M)
                *reinterpret_cast<float2*>(&C[(size_t)gr0 * Nc + gc]) =
                    make_float2(acc[mi][ni][0] + b0, acc[mi][ni][1] + b1);
            if (gr0 + 8 < M)
                *reinterpret_cast<float2*>(&C[(size_t)(gr0 + 8) * Nc + gc]) =
                    make_float2(acc[mi][ni][2] + b0, acc[mi][ni][3] + b1);
        }
}

// ============================================================================
// repack: RoPE q,k -> fp16 (bh,n,d);  v -> fp16 transposed (bh,d,n) + ones row
// grid (33 n-tiles of 32, 384 bh), 256 threads.
// ============================================================================
__global__ __launch_bounds__(256)
void repack(const float* __restrict__ qkv, const float* __restrict__ fcos,
            const float* __restrict__ fsin, __half* __restrict__ qh,
            __half* __restrict__ kh, __half* __restrict__ vt) {
    __shared__ __half svt[64 * 40];   // [d][32 n], stride 40 halves
    const int tid = threadIdx.x;
    const int n0 = blockIdx.x * 32, bh = blockIdx.y;
    const int b = bh / Hv, h = bh % Hv;

    // q,k RoPE: 2 parts x 32 n x 32 d-pairs = 2048 slots
    #pragma unroll
    for (int l = 0; l < 8; ++l) {
        int idx = tid + l * 256;
        int part = idx >> 10, rem = idx & 1023;
        int nl = rem >> 5, i = rem & 31;
        int n = n0 + nl;
        if (n < Nv) {
            float2 v = *reinterpret_cast<const float2*>(
                &qkv[((size_t)(b * Nv + n) * 3 + part) * DIMv + h * Dv + 2 * i]);
            float x0, x1;
            if (n == 0) { x0 = v.x; x1 = v.y; }
            else {
                float c = fcos[(size_t)(n - 1) * 32 + i];
                float s = fsin[(size_t)(n - 1) * 32 + i];
                x0 = v.x * c - v.y * s;
                x1 = v.x * s + v.y * c;
            }
            __half* dst = part ? kh : qh;
            *reinterpret_cast<__half2*>(
                &dst[((size_t)bh * Nv + n) * Dv + 2 * i]) = __floats2half2_rn(x0, x1);
        }
    }

    // v: load (n,d), store transposed via smem
    #pragma unroll
    for (int l = 0; l < 8; ++l) {
        int e = tid + l * 256;
        int nl = e >> 6, d = e & 63;
        int n = n0 + nl;
        float val = 0.f;
        if (n < Nv)
            val = qkv[((size_t)(b * Nv + n) * 3 + 2) * DIMv + h * Dv + d];
        svt[d * 40 + nl] = __float2half_rn(val);
    }
    __syncthreads();
    {
        int d = tid >> 2, seg = (tid & 3) * 8;
        int nb = n0 + seg;
        __half* dst = &vt[(size_t)bh * 72 * NP + (size_t)d * NP + nb];
        if (nb + 7 < Nv) {
            *reinterpret_cast<uint4*>(dst) =
                *reinterpret_cast<uint4*>(&svt[d * 40 + seg]);
        } else {
            for (int j = 0; j < 8; ++j)
                if (nb + j < Nv) dst[j] = svt[d * 40 + seg + j];
        }
    }
    if (tid < 32) {
        int n = n0 + tid;
        if (n < Nv)
            vt[(size_t)bh * 72 * NP + (size_t)64 * NP + n] = __float2half(1.0f);
    }
}

// ============================================================================
// feature GEMM: per (bh):  F = relu( X[1025x64] @ projS[64x64]^T ) + 1e-6
// grid (9 n-tiles, 384 bh, 2: 0=q->qf (n,j), 1=k->kfT (j,n) transposed)
// ============================================================================
__global__ __launch_bounds__(256)
void feat_gemm(const __half* __restrict__ qh, const __half* __restrict__ kh,
               const __half* __restrict__ projS,
               __half* __restrict__ qf, __half* __restrict__ kft) {
    __shared__ char fsm[24576];                    // A 16KB | B 8KB (reused for transpose)
    const uint32_t base = s2u(fsm), bB = base + 16384;
    const int tid = threadIdx.x, warp = tid >> 5, lane = tid & 31;
    const int n0 = blockIdx.x * 128, bh = blockIdx.y, qk = blockIdx.z;
    const __half* A = (qk ? kh : qh) + (size_t)bh * Nv * Dv;

    // stage A (128x64) + B (64x64)
    #pragma unroll
    for (int l = 0; l < 4; ++l) {
        int idx = tid + l * 256;       // 0..1023
        int r = idx >> 3, s = idx & 7;
        int n = n0 + r, ok = (n < Nv);
        cp16p(base + chunk_off(s, r), A + (size_t)(ok ? n : 0) * Dv + s * 8, ok ? 16 : 0);
    }
    #pragma unroll
    for (int l = 0; l < 2; ++l) {
        int idx = tid + l * 256;       // 0..511
        int r = idx >> 3, s = idx & 7;
        cp16(bB + chunk_off64(s, r), projS + (size_t)r * Dv + s * 8);
    }
    CPCOMMIT(); cpwait(0); __syncthreads();

    const int wm = (warp >> 1) * 32, wn = (warp & 1) * 32;
    const int a_r = lane & 15, a_s = lane >> 4;
    const int b_r = lane & 7,  b_s = (lane >> 3) & 1;
    float acc[2][4][4];
    #pragma unroll
    for (int i = 0; i < 2; ++i)
        #pragma unroll
        for (int j = 0; j < 4; ++j)
            #pragma unroll
            for (int c = 0; c < 4; ++c) acc[i][j][c] = 0.f;

    #pragma unroll
    for (int ks = 0; ks < 4; ++ks) {
        uint32_t af[2][4], bf[4][2];
        #pragma unroll
        for (int ni = 0; ni < 4; ++ni)
            ldm2(bf[ni], bB + chunk_off64(2 * ks + b_s, wn + ni * 8 + b_r));
        #pragma unroll
        for (int mi = 0; mi < 2; ++mi)
            ldm4(af[mi], base + chunk_off(2 * ks + a_s, wm + mi * 16 + a_r));
        #pragma unroll
        for (int mi = 0; mi < 2; ++mi)
            #pragma unroll
            for (int ni = 0; ni < 4; ++ni)
                mma16816(acc[mi][ni], af[mi], bf[ni]);
    }

    const int er = lane >> 2, ec = 2 * (lane & 3);
    if (qk == 0) {
        // qf (n, j) fp16
        #pragma unroll
        for (int mi = 0; mi < 2; ++mi)
            #pragma unroll
            for (int ni = 0; ni < 4; ++ni) {
                int row = wm + mi * 16 + er, col = wn + ni * 8 + ec;
                int n = n0 + row;
                if (n < Nv) {
                    float v0 = fmaxf(acc[mi][ni][0], 0.f) + 1e-6f;
                    float v1 = fmaxf(acc[mi][ni][1], 0.f) + 1e-6f;
                    *reinterpret_cast<__half2*>(
                        &qf[((size_t)bh * Nv + n) * Dv + col]) = __floats2half2_rn(v0, v1);
                }
                if (n + 8 < Nv) {
                    float v2 = fmaxf(acc[mi][ni][2], 0.f) + 1e-6f;
                    float v3 = fmaxf(acc[mi][ni][3], 0.f) + 1e-6f;
                    *reinterpret_cast<__half2*>(
                        &qf[((size_t)bh * Nv + n + 8) * Dv + col]) = __floats2half2_rn(v2, v3);
                }
            }
    } else {
        // kfT (j, n): transpose via smem [64 j][stride 136]
        __syncthreads();
        __half* sm16 = reinterpret_cast<__half*>(fsm);
        #pragma unroll
        for (int mi = 0; mi < 2; ++mi)
            #pragma unroll
            for (int ni = 0; ni < 4; ++ni) {
                int row = wm + mi * 16 + er, col = wn + ni * 8 + ec;
                sm16[(col)     * 136 + row    ] = __float2half_rn(fmaxf(acc[mi][ni][0], 0.f) + 1e-6f);
                sm16[(col + 1) * 136 + row    ] = __float2half_rn(fmaxf(acc[mi][ni][1], 0.f) + 1e-6f);
                sm16[(col)     * 136 + row + 8] = __float2half_rn(fmaxf(acc[mi][ni][2], 0.f) + 1e-6f);
                sm16[(col + 1) * 136 + row + 8] = __float2half_rn(fmaxf(acc[mi][ni][3], 0.f) + 1e-6f);
            }
        __syncthreads();
        int j = tid >> 2, seg = (tid & 3) * 32;
        __half* dst = &kft[(size_t)bh * Dv * NP + (size_t)j * NP + n0 + seg];
        #pragma unroll
        for (int i = 0; i < 32; i += 2) {
            int n = n0 + seg + i;
            if (n + 1 < Nv)
                *reinterpret_cast<__half2*>(dst + i) =
                    *reinterpret_cast<const __half2*>(&sm16[j * 136 + seg + i]);
            else if (n < Nv)
                dst[i] = sm16[j * 136 + seg + i];
        }
    }
}

// ============================================================================
// ctx GEMM: per bh:  C[r][d] = sum_n vt[r,n] * kfT[d,n]   (K = 1056)
// rows 0-63 = ctx[e][d], row 64 = ksum[d] (ones row), rows 65+ = 0.
// grid (384), 256 threads, 4-stage pipeline, M=128 N=64.
// ============================================================================
#define CSTG_B 12288     // A 8KB + B 4KB
__global__ __launch_bounds__(256)
void ctx_gemm(const __half* __restrict__ vt, const __half* __restrict__ kft,
              __half* __restrict__ ctxh) {
    __shared__ char csm[4 * CSTG_B];
    const uint32_t base = s2u(csm);
    const int tid = threadIdx.x, warp = tid >> 5, lane = tid & 31;
    const int bh = blockIdx.x;
    const __half* Av = vt  + (size_t)bh * 72 * NP;
    const __half* Bk = kft + (size_t)bh * Dv * NP;
    const int nk = NP / 32;    // 33

    auto stage = [&](int t, int sb) {
        const int k0 = t * 32;
        const uint32_t sbase = base + sb * CSTG_B;
        #pragma unroll
        for (int l = 0; l < 3; ++l) {
            int idx = tid + l * 256;          // 0..767
            if (idx < 512) {
                int r = idx >> 2, s = idx & 3;
                int ok = (r < 72);
                cp16p(sbase + chunk_off(s, r),
                      Av + (size_t)(ok ? r : 0) * NP + k0 + s * 8, ok ? 16 : 0);
            } else {
                int j = idx - 512;
                int r = j >> 2, s = j & 3;
                cp16(sbase + 8192 + chunk_off64(s, r),
                     Bk + (size_t)r * NP + k0 + s * 8);
            }
        }
    };

    stage(0, 0); CPCOMMIT();
    stage(1, 1); CPCOMMIT();
    stage(2, 2); CPCOMMIT();

    const int wm = (warp >> 1) * 32, wn = (warp & 1) * 32;
    const int a_r = lane & 15, a_s = lane >> 4;
    const int b_r = lane & 7,  b_s = (lane >> 3) & 1;
    float acc[2][4][4];
    #pragma unroll
    for (int i = 0; i < 2; ++i)
        #pragma unroll
        for (int j = 0; j < 4; ++j)
            #pragma unroll
            for (int c = 0; c < 4; ++c) acc[i][j][c] = 0.f;

    for (int t = 0; t < nk; ++t) {
        cpwait(min(nk - 1 - t, 2));
        __syncthreads();
        const uint32_t pb = base + (t & 3) * CSTG_B;
        #pragma unroll
        for (int ks = 0; ks < 2; ++ks) {
            uint32_t af[2][4], bf[4][2];
            #pragma unroll
            for (int ni = 0; ni < 4; ++ni)
                ldm2(bf[ni], pb + 8192 + chunk_off64(2 * ks + b_s, wn + ni * 8 + b_r));
            #pragma unroll
            for (int mi = 0; mi < 2; ++mi)
                ldm4(af[mi], pb + chunk_off(2 * ks + a_s, wm + mi * 16 + a_r));
            #pragma unroll
            for (int mi = 0; mi < 2; ++mi)
                #pragma unroll
                for (int ni = 0; ni < 4; ++ni)
                    mma16816(acc[mi][ni], af[mi], bf[ni]);
        }
        __syncthreads();
        if (t + 3 < nk) { stage(t + 3, (t + 3) & 3); CPCOMMIT(); }
    }

    const int er = lane >> 2, ec = 2 * (lane & 3);
    #pragma unroll
    for (int mi = 0; mi < 2; ++mi)
        #pragma unroll
        for (int ni = 0; ni < 4; ++ni) {
            int row = wm + mi * 16 + er, col = wn + ni * 8 + ec;
            if (row < 72)
                *reinterpret_cast<__half2*>(&ctxh[(size_t)bh * 128 * Dv + row * Dv + col]) =
                    __floats2half2_rn(acc[mi][ni][0], acc[mi][ni][1]);
            if (row + 8 < 72)
                *reinterpret_cast<__half2*>(&ctxh[(size_t)bh * 128 * Dv + (row + 8) * Dv + col]) =
                    __floats2half2_rn(acc[mi][ni][2], acc[mi][ni][3]);
        }
}

// ============================================================================
// out GEMM: per bh:  C[n][c] = sum_d qf[n,d] * ctxh[c,d], c in 0..127;
// col 64 = denom;  ah[b,n,h*64+e] = C[n][e] / C[n][64]  (fp16)
// grid (9 n-tiles, 384 bh), 256 threads, M=128 N=128 K=64 single stage.
// ============================================================================
__global__ __launch_bounds__(256)
void out_gemm(const __half* __restrict__ qf, const __half* __restrict__ ctxh,
              __half* __restrict__ ah) {
    __shared__ char osm[32768];     // A 16KB | B 16KB
    __shared__ float sden[128];
    const uint32_t base = s2u(osm), bB = base + 16384;
    const int tid = threadIdx.x, warp = tid >> 5, lane = tid & 31;
    const int n0 = blockIdx.x * 128, bh = blockIdx.y;
    const int b = bh / Hv, h = bh % Hv;
    const __half* A = qf   + (size_t)bh * Nv * Dv;
    const __half* Bm = ctxh + (size_t)bh * 128 * Dv;

    #pragma unroll
    for (int l = 0; l < 4; ++l) {
        int idx = tid + l * 256;
        int r = idx >> 3, s = idx & 7;
        int n = n0 + r, ok = (n < Nv);
        cp16p(base + chunk_off(s, r), A + (size_t)(ok ? n : 0) * Dv + s * 8, ok ? 16 : 0);
    }
    #pragma unroll
    for (int l = 0; l < 4; ++l) {
        int idx = tid + l * 256;
        int r = idx >> 3, s = idx & 7;
        cp16(bB + chunk_off(s, r), Bm + (size_t)r * Dv + s * 8);
    }
    CPCOMMIT(); cpwait(0); __syncthreads();

    const int wm = (warp >> 2) * 64, wn = (warp & 3) * 32;
    const int a_r = lane & 15, a_s = lane >> 4;
    const int b_r = lane & 7,  b_s = (lane >> 3) & 1;
    float acc[4][4][4];
    #pragma unroll
    for (int i = 0; i < 4; ++i)
        #pragma unroll
        for (int j = 0; j < 4; ++j)
            #pragma unroll
            for (int c = 0; c < 4; ++c) acc[i][j][c] = 0.f;

    #pragma unroll
    for (int ks = 0; ks < 4; ++ks) {
        uint32_t af[4][4], bf[4][2];
        #pragma unroll
        for (int ni = 0; ni < 4; ++ni)
            ldm2(bf[ni], bB + chunk_off(2 * ks + b_s, wn + ni * 8 + b_r));
        #pragma unroll
        for (int mi = 0; mi < 4; ++mi)
            ldm4(af[mi], base + chunk_off(2 * ks + a_s, wm + mi * 16 + a_r));
        #pragma unroll
        for (int mi = 0; mi < 4; ++mi)
            #pragma unroll
            for (int ni = 0; ni < 4; ++ni)
                mma16816(acc[mi][ni], af[mi], bf[ni]);
    }

    const int er = lane >> 2, ec = 2 * (lane & 3);
    // publish denominators (column 64 lives in warps with wn==64, ni==0, ec==0)
    if (wn == 64 && (lane & 3) == 0) {
        #pragma unroll
        for (int mi = 0; mi < 4; ++mi) {
            sden[wm + mi * 16 + er]     = acc[mi][0][0];
            sden[wm + mi * 16 + er + 8] = acc[mi][0][2];
        }
    }
    __syncthreads();
    if (wn < 64) {
        #pragma unroll
        for (int mi = 0; mi < 4; ++mi)
            #pragma unroll
            for (int ni = 0; ni < 4; ++ni) {
                int row = wm + mi * 16 + er, col = wn + ni * 8 + ec;
                int n = n0 + row;
                if (n < Nv) {
                    float inv = 1.f / sden[row];
                    *reinterpret_cast<__half2*>(
                        &ah[((size_t)(b * Nv + n)) * DIMv + h * Dv + col]) =
                        __floats2half2_rn(acc[mi][ni][0] * inv, acc[mi][ni][1] * inv);
                }
                if (n + 8 < Nv) {
                    float inv = 1.f / sden[row + 8];
                    *reinterpret_cast<__half2*>(
                        &ah[((size_t)(b * Nv + n + 8)) * DIMv + h * Dv + col]) =
                        __floats2half2_rn(acc[mi][ni][2] * inv, acc[mi][ni][3] * inv);
                }
            }
    }
}

// ============================================================================
// launcher
// ============================================================================
extern "C" void kernel_launch(void* const* d_in, const int* in_sizes, int n_in,
                              void* d_out, int out_size) {
    const float* x     = (const float*)d_in[0];
    const float* W_qkv = (const float*)d_in[1];
    const float* W_out = (const float*)d_in[2];
    const float* b_out = (const float*)d_in[3];
    const float* proj  = (const float*)d_in[4];
    const float* fcos  = (const float*)d_in[5];
    const float* fsin  = (const float*)d_in[6];
    float* out = (float*)d_out;

    float* p_qkv;
    cudaGetSymbolAddress((void**)&p_qkv, g_qkv);
    __half *xh, *wqh, *woh, *projh, *qh, *kh, *vt, *qfh, *kft, *ctxh, *ah;
    cudaGetSymbolAddress((void**)&xh,    g_xh);
    cudaGetSymbolAddress((void**)&wqh,   g_wqh);
    cudaGetSymbolAddress((void**)&woh,   g_woh);
    cudaGetSymbolAddress((void**)&projh, g_projh);
    cudaGetSymbolAddress((void**)&qh,    g_qh);
    cudaGetSymbolAddress((void**)&kh,    g_kh);
    cudaGetSymbolAddress((void**)&vt,    g_vt);
    cudaGetSymbolAddress((void**)&qfh,   g_qfh);
    cudaGetSymbolAddress((void**)&kft,   g_kft);
    cudaGetSymbolAddress((void**)&ctxh,  g_ctxh);
    cudaGetSymbolAddress((void**)&ah,    g_ah);

    cudaFuncSetAttribute(gemm_hmma<false>,
                         cudaFuncAttributeMaxDynamicSharedMemorySize, GSMEM);
    cudaFuncSetAttribute(gemm_hmma<true>,
                         cudaFuncAttributeMaxDynamicSharedMemorySize, GSMEM);

    // 0) conversions
    conv_fp16<<<2048, 256>>>(x,     xh,  (size_t)M1 * DIMv / 4);
    conv_fp16<<<512,  256>>>(W_qkv, wqh, (size_t)G3 * DIMv / 4);
    conv_fp16<<<256,  256>>>(W_out, woh, (size_t)DIMv * DIMv / 4);
    conv_proj<<<16,   256>>>(proj, projh);

    // 1) QKV projection (fp16 HMMA)
    {
        dim3 grid(G3 / 128, (M1 + 127) / 128);
        gemm_hmma<false><<<grid, 256, GSMEM>>>(xh, wqh, nullptr, p_qkv, M1, G3, DIMv);
    }
    // 2) RoPE + repack (qh, kh, vT+ones)
    {
        dim3 grid(33, BH);
        repack<<<grid, 256>>>(p_qkv, fcos, fsin, qh, kh, vt);
    }
    // 3) feature maps (HMMA): qf and kfT
    {
        dim3 grid(9, BH, 2);
        feat_gemm<<<grid, 256>>>(qh, kh, projh, qfh, kft);
    }
    // 4) context + ksum (HMMA, ones-row trick)
    ctx_gemm<<<BH, 256>>>(vt, kft, ctxh);
    // 5) output contraction + denom + divide (HMMA) -> ah fp16
    {
        dim3 grid(9, BH);
        out_gemm<<<grid, 256>>>(qfh, ctxh, ah);
    }
    // 6) output projection + bias (fp16 HMMA)
    {
        dim3 grid(DIMv / 128, (M1 + 127) / 128);
        gemm_hmma<true><<<grid, 256, GSMEM>>>(ah, woh, b_out, out, M1, DIMv, DIMv);
    }
}

// round 8
// speedup vs baseline: 12.2524x; 1.0651x over previous
#include <cuda_runtime.h>
#include <cuda_fp16.h>
#include <cstdint>
#include <cstddef>

// Problem constants
#define Bv   32
#define Nv   1025
#define DIMv 768
#define Hv   12
#define Dv   64
#define M1   (Bv * Nv)          // 32800 tokens
#define G3   (3 * Hv * Dv)      // 2304
#define BH   (Bv * Hv)          // 384
#define NP   1056               // n padded to mult of 32

// -------- scratch (device globals; zero-initialized at load; pads of vt/kft/
//          ctxh are NEVER written and must stay zero — do not memset) --------
__device__ __half g_xh  [(size_t)M1 * DIMv];
__device__ __half g_wqh [(size_t)G3 * DIMv];
__device__ __half g_woh [(size_t)DIMv * DIMv];
__device__ __half g_projh[(size_t)Dv * Dv];             // proj * 64^-0.25
__device__ __half g_qh  [(size_t)BH * Nv * Dv];         // roped q (bh,n,d)
__device__ __half g_kh  [(size_t)BH * Nv * Dv];         // roped k
__device__ __half g_vtmp[(size_t)BH * Nv * Dv];         // v (bh,n,d)
__device__ __half g_vt  [(size_t)BH * 72 * NP];         // v^T (bh,d,n); row64=ones
__device__ __half g_qfh [(size_t)BH * Nv * Dv];         // feature(q) (bh,n,j)
__device__ __half g_kft [(size_t)BH * Dv * NP];         // feature(k)^T (bh,j,n)
__device__ __half g_ctxh[(size_t)BH * 128 * Dv];        // rows0-63 ctx, row64 ksum
__device__ __half g_ah  [(size_t)M1 * DIMv];            // attn out fp16

// ============================================================================
// PTX helpers
// ============================================================================
__device__ __forceinline__ uint32_t s2u(const void* p) {
    uint32_t a;
    asm("{ .reg .u64 t; cvta.to.shared.u64 t, %1; cvt.u32.u64 %0, t; }"
        : "=r"(a) : "l"(p));
    return a;
}
__device__ __forceinline__ void cp16(uint32_t dst, const void* src) {
    asm volatile("cp.async.cg.shared.global [%0], [%1], 16;"
                 :: "r"(dst), "l"(src) : "memory");
}
__device__ __forceinline__ void cp16p(uint32_t dst, const void* src, int p) {
    asm volatile("cp.async.cg.shared.global [%0], [%1], 16, %2;"
                 :: "r"(dst), "l"(src), "r"(p) : "memory");
}
#define CPCOMMIT() asm volatile("cp.async.commit_group;" ::: "memory")
__device__ __forceinline__ void cpwait(int n) {
    if (n >= 2)      asm volatile("cp.async.wait_group 2;" ::: "memory");
    else if (n == 1) asm volatile("cp.async.wait_group 1;" ::: "memory");
    else             asm volatile("cp.async.wait_group 0;" ::: "memory");
}
__device__ __forceinline__ void ldm4(uint32_t* r, uint32_t a) {
    asm volatile("ldmatrix.sync.aligned.m8n8.x4.shared.b16 {%0,%1,%2,%3}, [%4];"
                 : "=r"(r[0]), "=r"(r[1]), "=r"(r[2]), "=r"(r[3]) : "r"(a));
}
__device__ __forceinline__ void ldm2(uint32_t* r, uint32_t a) {
    asm volatile("ldmatrix.sync.aligned.m8n8.x2.shared.b16 {%0,%1}, [%2];"
                 : "=r"(r[0]), "=r"(r[1]) : "r"(a));
}
__device__ __forceinline__ void mma16816(float* d, const uint32_t* a,
                                         const uint32_t* b) {
    asm volatile(
        "mma.sync.aligned.m16n8k16.row.col.f32.f16.f16.f32 "
        "{%0,%1,%2,%3},{%4,%5,%6,%7},{%8,%9},{%0,%1,%2,%3};"
        : "+f"(d[0]), "+f"(d[1]), "+f"(d[2]), "+f"(d[3])
        : "r"(a[0]), "r"(a[1]), "r"(a[2]), "r"(a[3]), "r"(b[0]), "r"(b[1]));
}

// 16B-chunk layouts. Old layout (middle kernels, s paired with r^(2s)):
__device__ __forceinline__ uint32_t chunk_off(int s, int r) {      // 128-row plane
    return (uint32_t)(((s << 7) + (r ^ (s << 1))) << 4);
}
__device__ __forceinline__ uint32_t chunk_off64(int s, int r) {    // 64-row plane
    return (uint32_t)(((s << 6) + (r ^ (s << 1))) << 4);
}
// New BK=64 layout: plane 128 rows x 8 slabs; conflict-free both sides.
__device__ __forceinline__ uint32_t chunk_off8(int s, int r) {
    return (uint32_t)(((s << 7) + (r ^ s)) << 4);
}

// ============================================================================
// conversions
// ============================================================================
__global__ __launch_bounds__(256)
void conv_fp16(const float* __restrict__ s, __half* __restrict__ h, size_t n4) {
    size_t i = (size_t)blockIdx.x * blockDim.x + threadIdx.x;
    size_t stride = (size_t)gridDim.x * blockDim.x;
    for (; i < n4; i += stride) {
        float4 v = reinterpret_cast<const float4*>(s)[i];
        reinterpret_cast<__half2*>(h)[2 * i]     = __floats2half2_rn(v.x, v.y);
        reinterpret_cast<__half2*>(h)[2 * i + 1] = __floats2half2_rn(v.z, v.w);
    }
}
__global__ __launch_bounds__(256)
void conv_proj(const float* __restrict__ p, __half* __restrict__ ph) {
    int i = blockIdx.x * 256 + threadIdx.x;
    if (i < Dv * Dv) ph[i] = __float2half_rn(p[i] * 0.35355339059327379f);
}

// ============================================================================
// GEMM core config: CTA 128x128, BK=64, 3-stage cp.async (32KB/stage)
// ============================================================================
#define BKi     64
#define PLANE_B 16384
#define STAGE_B (2 * PLANE_B)
#define NSTAGE  3
#define GSMEM   (NSTAGE * STAGE_B)

// ---- shared mainloop macro-like structure is written out in each kernel ----

// ============================================================================
// GEMM1 fused: qkv = xh @ wqh^T, RoPE applied in epilogue, fp16 outputs:
//   part0 -> qh (bh,n,d) roped; part1 -> kh roped; part2 -> vtmp (bh,n,d)
// grid (18, 257), 256 threads.
// ============================================================================
__global__ __launch_bounds__(256, 2)
void gemm_qkv(const __half* __restrict__ Ah, const __half* __restrict__ Bh,
              const float* __restrict__ fcos, const float* __restrict__ fsin,
              __half* __restrict__ qh, __half* __restrict__ kh,
              __half* __restrict__ vtmp) {
    extern __shared__ char dsm[];
    const uint32_t base = s2u(dsm);
    const int tid  = threadIdx.x;
    const int warp = tid >> 5, lane = tid & 31;
    const int row0 = blockIdx.y * 128, col0 = blockIdx.x * 128;
    const int wm = (warp >> 2) * 64, wn = (warp & 3) * 32;
    const int K = DIMv, nk = K / BKi;   // 12

    float acc[4][4][4];
    #pragma unroll
    for (int i = 0; i < 4; ++i)
        #pragma unroll
        for (int j = 0; j < 4; ++j)
            #pragma unroll
            for (int c = 0; c < 4; ++c) acc[i][j][c] = 0.f;

    auto stage = [&](int t, int sb) {
        const int k0 = t * BKi;
        const uint32_t sbase = base + sb * STAGE_B;
        #pragma unroll
        for (int l = 0; l < 8; ++l) {
            int idx = tid + l * 256;
            int p = idx >> 10, cid = idx & 1023;
            int r = cid >> 3, s = cid & 7;
            uint32_t dst = sbase + p * PLANE_B + chunk_off8(s, r);
            if (p == 0) {
                int gr = row0 + r, ok = (gr < M1);
                cp16p(dst, Ah + (size_t)(ok ? gr : 0) * K + k0 + s * 8, ok ? 16 : 0);
            } else {
                cp16(dst, Bh + (size_t)(col0 + r) * K + k0 + s * 8);
            }
        }
    };

    stage(0, 0); CPCOMMIT();
    stage(1, 1); CPCOMMIT();

    const int a_r = lane & 15, a_s = lane >> 4;
    const int b_r = lane & 7,  b_s = (lane >> 3) & 1;

    for (int t = 0; t < nk; ++t) {
        cpwait(min(nk - 1 - t, 1));
        __syncthreads();
        const uint32_t pb = base + (t % NSTAGE) * STAGE_B;
        #pragma unroll
        for (int ks = 0; ks < 4; ++ks) {
            uint32_t af[4][4], bf[4][2];
            #pragma unroll
            for (int ni = 0; ni < 4; ++ni)
                ldm2(bf[ni], pb + PLANE_B + chunk_off8(2 * ks + b_s, wn + ni * 8 + b_r));
            #pragma unroll
            for (int mi = 0; mi < 4; ++mi)
                ldm4(af[mi], pb + chunk_off8(2 * ks + a_s, wm + mi * 16 + a_r));
            #pragma unroll
            for (int mi = 0; mi < 4; ++mi)
                #pragma unroll
                for (int ni = 0; ni < 4; ++ni)
                    mma16816(acc[mi][ni], af[mi], bf[ni]);
        }
        if (t + 2 < nk) { stage(t + 2, (t + 2) % NSTAGE); CPCOMMIT(); }
    }

    // ---- fused epilogue: RoPE + fp16 scatter ----
    const int er = lane >> 2, ec = 2 * (lane & 3);
    const int part = col0 / DIMv;              // tile entirely in one part
    __half* dstbase = (part == 0) ? qh : (part == 1) ? kh : vtmp;

    int rb[8], rn[8];
    #pragma unroll
    for (int mi = 0; mi < 4; ++mi) {
        int gr = row0 + wm + mi * 16 + er;
        rb[2 * mi] = gr / Nv; rn[2 * mi] = gr - rb[2 * mi] * Nv;
        gr += 8;
        rb[2 * mi + 1] = gr / Nv; rn[2 * mi + 1] = gr - rb[2 * mi + 1] * Nv;
    }

    #pragma unroll
    for (int mi = 0; mi < 4; ++mi)
        #pragma unroll
        for (int ni = 0; ni < 4; ++ni) {
            int gc = col0 + wn + ni * 8 + ec;
            int rem = gc - part * DIMv;
            int h = rem >> 6, d = rem & 63, i = d >> 1;
            #pragma unroll
            for (int hf = 0; hf < 2; ++hf) {
                int gr = row0 + wm + mi * 16 + er + 8 * hf;
                if (gr >= M1) continue;
                int b = rb[2 * mi + hf], n = rn[2 * mi + hf];
                float v0 = acc[mi][ni][2 * hf], v1 = acc[mi][ni][2 * hf + 1];
                if (part < 2 && n > 0) {
                    float c = __ldg(&fcos[(size_t)(n - 1) * 32 + i]);
                    float s = __ldg(&fsin[(size_t)(n - 1) * 32 + i]);
                    float t0 = v0 * c - v1 * s;
                    v1 = v0 * s + v1 * c;
                    v0 = t0;
                }
                *reinterpret_cast<__half2*>(
                    &dstbase[(((size_t)b * Hv + h) * Nv + n) * Dv + d]) =
                    __floats2half2_rn(v0, v1);
            }
        }
}

// ============================================================================
// GEMM2 (generic): C = A @ B^T + bias, fp32 out. Same BK=64 core.
// ============================================================================
__global__ __launch_bounds__(256, 2)
void gemm_out(const __half* __restrict__ Ah, const __half* __restrict__ Bh,
              const float* __restrict__ bias, float* __restrict__ C,
              int M, int Nc, int K) {
    extern __shared__ char dsm[];
    const uint32_t base = s2u(dsm);
    const int tid  = threadIdx.x;
    const int warp = tid >> 5, lane = tid & 31;
    const int row0 = blockIdx.y * 128, col0 = blockIdx.x * 128;
    const int wm = (warp >> 2) * 64, wn = (warp & 3) * 32;
    const int nk = K / BKi;

    float acc[4][4][4];
    #pragma unroll
    for (int i = 0; i < 4; ++i)
        #pragma unroll
        for (int j = 0; j < 4; ++j)
            #pragma unroll
            for (int c = 0; c < 4; ++c) acc[i][j][c] = 0.f;

    auto stage = [&](int t, int sb) {
        const int k0 = t * BKi;
        const uint32_t sbase = base + sb * STAGE_B;
        #pragma unroll
        for (int l = 0; l < 8; ++l) {
            int idx = tid + l * 256;
            int p = idx >> 10, cid = idx & 1023;
            int r = cid >> 3, s = cid & 7;
            uint32_t dst = sbase + p * PLANE_B + chunk_off8(s, r);
            if (p == 0) {
                int gr = row0 + r, ok = (gr < M);
                cp16p(dst, Ah + (size_t)(ok ? gr : 0) * K + k0 + s * 8, ok ? 16 : 0);
            } else {
                cp16(dst, Bh + (size_t)(col0 + r) * K + k0 + s * 8);
            }
        }
    };

    stage(0, 0); CPCOMMIT();
    stage(1, 1); CPCOMMIT();

    const int a_r = lane & 15, a_s = lane >> 4;
    const int b_r = lane & 7,  b_s = (lane >> 3) & 1;

    for (int t = 0; t < nk; ++t) {
        cpwait(min(nk - 1 - t, 1));
        __syncthreads();
        const uint32_t pb = base + (t % NSTAGE) * STAGE_B;
        #pragma unroll
        for (int ks = 0; ks < 4; ++ks) {
            uint32_t af[4][4], bf[4][2];
            #pragma unroll
            for (int ni = 0; ni < 4; ++ni)
                ldm2(bf[ni], pb + PLANE_B + chunk_off8(2 * ks + b_s, wn + ni * 8 + b_r));
            #pragma unroll
            for (int mi = 0; mi < 4; ++mi)
                ldm4(af[mi], pb + chunk_off8(2 * ks + a_s, wm + mi * 16 + a_r));
            #pragma unroll
            for (int mi = 0; mi < 4; ++mi)
                #pragma unroll
                for (int ni = 0; ni < 4; ++ni)
                    mma16816(acc[mi][ni], af[mi], bf[ni]);
        }
        if (t + 2 < nk) { stage(t + 2, (t + 2) % NSTAGE); CPCOMMIT(); }
    }

    const int er = lane >> 2, ec = 2 * (lane & 3);
    #pragma unroll
    for (int mi = 0; mi < 4; ++mi)
        #pragma unroll
        for (int ni = 0; ni < 4; ++ni) {
            int gc = col0 + wn + ni * 8 + ec;
            float b0 = bias[gc], b1 = bias[gc + 1];
            int gr0 = row0 + wm + mi * 16 + er;
            if (gr0 < M)
                *reinterpret_cast<float2*>(&C[(size_t)gr0 * Nc + gc]) =
                    make_float2(acc[mi][ni][0] + b0, acc[mi][ni][1] + b1);
            if (gr0 + 8 < M)
                *reinterpret_cast<float2*>(&C[(size_t)(gr0 + 8) * Nc + gc]) =
                    make_float2(acc[mi][ni][2] + b0, acc[mi][ni][3] + b1);
        }
}

// ============================================================================
// v transpose: vtmp (bh,n,d) -> vt (bh,d,n) + ones row 64.  grid (33, 384).
// ============================================================================
__global__ __launch_bounds__(256)
void vtrans(const __half* __restrict__ vtmp, __half* __restrict__ vt) {
    __shared__ __half sv[64 * 40];
    const int tid = threadIdx.x;
    const int n0 = blockIdx.x * 32, bh = blockIdx.y;

    int nl = tid >> 3, seg = (tid & 7) * 8;
    int n = n0 + nl;
    __half tmp[8];
    if (n < Nv) {
        *reinterpret_cast<uint4*>(tmp) = *reinterpret_cast<const uint4*>(
            &vtmp[((size_t)bh * Nv + n) * Dv + seg]);
    } else {
        #pragma unroll
        for (int j = 0; j < 8; ++j) tmp[j] = __float2half(0.f);
    }
    #pragma unroll
    for (int j = 0; j < 8; ++j) sv[(seg + j) * 40 + nl] = tmp[j];
    __syncthreads();

    int d = tid >> 2, sg = (tid & 3) * 8;
    int nb = n0 + sg;
    __half* dst = &vt[(size_t)bh * 72 * NP + (size_t)d * NP + nb];
    if (nb + 7 < Nv) {
        *reinterpret_cast<uint4*>(dst) = *reinterpret_cast<uint4*>(&sv[d * 40 + sg]);
    } else {
        for (int j = 0; j < 8; ++j)
            if (nb + j < Nv) dst[j] = sv[d * 40 + sg + j];
    }
    if (tid < 32 && n0 + tid < Nv)
        vt[(size_t)bh * 72 * NP + (size_t)64 * NP + n0 + tid] = __float2half(1.f);
}

// ============================================================================
// feature GEMM (unchanged): F = relu(X @ projS^T) + 1e-6
// grid (9, 384, 2): z=0 -> qf (n,j); z=1 -> kfT (j,n)
// ============================================================================
__global__ __launch_bounds__(256)
void feat_gemm(const __half* __restrict__ qh, const __half* __restrict__ kh,
               const __half* __restrict__ projS,
               __half* __restrict__ qf, __half* __restrict__ kft) {
    __shared__ char fsm[24576];
    const uint32_t base = s2u(fsm), bB = base + 16384;
    const int tid = threadIdx.x, warp = tid >> 5, lane = tid & 31;
    const int n0 = blockIdx.x * 128, bh = blockIdx.y, qk = blockIdx.z;
    const __half* A = (qk ? kh : qh) + (size_t)bh * Nv * Dv;

    #pragma unroll
    for (int l = 0; l < 4; ++l) {
        int idx = tid + l * 256;
        int r = idx >> 3, s = idx & 7;
        int n = n0 + r, ok = (n < Nv);
        cp16p(base + chunk_off(s, r), A + (size_t)(ok ? n : 0) * Dv + s * 8, ok ? 16 : 0);
    }
    #pragma unroll
    for (int l = 0; l < 2; ++l) {
        int idx = tid + l * 256;
        int r = idx >> 3, s = idx & 7;
        cp16(bB + chunk_off64(s, r), projS + (size_t)r * Dv + s * 8);
    }
    CPCOMMIT(); cpwait(0); __syncthreads();

    const int wm = (warp >> 1) * 32, wn = (warp & 1) * 32;
    const int a_r = lane & 15, a_s = lane >> 4;
    const int b_r = lane & 7,  b_s = (lane >> 3) & 1;
    float acc[2][4][4];
    #pragma unroll
    for (int i = 0; i < 2; ++i)
        #pragma unroll
        for (int j = 0; j < 4; ++j)
            #pragma unroll
            for (int c = 0; c < 4; ++c) acc[i][j][c] = 0.f;

    #pragma unroll
    for (int ks = 0; ks < 4; ++ks) {
        uint32_t af[2][4], bf[4][2];
        #pragma unroll
        for (int ni = 0; ni < 4; ++ni)
            ldm2(bf[ni], bB + chunk_off64(2 * ks + b_s, wn + ni * 8 + b_r));
        #pragma unroll
        for (int mi = 0; mi < 2; ++mi)
            ldm4(af[mi], base + chunk_off(2 * ks + a_s, wm + mi * 16 + a_r));
        #pragma unroll
        for (int mi = 0; mi < 2; ++mi)
            #pragma unroll
            for (int ni = 0; ni < 4; ++ni)
                mma16816(acc[mi][ni], af[mi], bf[ni]);
    }

    const int er = lane >> 2, ec = 2 * (lane & 3);
    if (qk == 0) {
        #pragma unroll
        for (int mi = 0; mi < 2; ++mi)
            #pragma unroll
            for (int ni = 0; ni < 4; ++ni) {
                int row = wm + mi * 16 + er, col = wn + ni * 8 + ec;
                int n = n0 + row;
                if (n < Nv) {
                    float v0 = fmaxf(acc[mi][ni][0], 0.f) + 1e-6f;
                    float v1 = fmaxf(acc[mi][ni][1], 0.f) + 1e-6f;
                    *reinterpret_cast<__half2*>(
                        &qf[((size_t)bh * Nv + n) * Dv + col]) = __floats2half2_rn(v0, v1);
                }
                if (n + 8 < Nv) {
                    float v2 = fmaxf(acc[mi][ni][2], 0.f) + 1e-6f;
                    float v3 = fmaxf(acc[mi][ni][3], 0.f) + 1e-6f;
                    *reinterpret_cast<__half2*>(
                        &qf[((size_t)bh * Nv + n + 8) * Dv + col]) = __floats2half2_rn(v2, v3);
                }
            }
    } else {
        __syncthreads();
        __half* sm16 = reinterpret_cast<__half*>(fsm);
        #pragma unroll
        for (int mi = 0; mi < 2; ++mi)
            #pragma unroll
            for (int ni = 0; ni < 4; ++ni) {
                int row = wm + mi * 16 + er, col = wn + ni * 8 + ec;
                sm16[(col)     * 136 + row    ] = __float2half_rn(fmaxf(acc[mi][ni][0], 0.f) + 1e-6f);
                sm16[(col + 1) * 136 + row    ] = __float2half_rn(fmaxf(acc[mi][ni][1], 0.f) + 1e-6f);
                sm16[(col)     * 136 + row + 8] = __float2half_rn(fmaxf(acc[mi][ni][2], 0.f) + 1e-6f);
                sm16[(col + 1) * 136 + row + 8] = __float2half_rn(fmaxf(acc[mi][ni][3], 0.f) + 1e-6f);
            }
        __syncthreads();
        int j = tid >> 2, seg = (tid & 3) * 32;
        __half* dst = &kft[(size_t)bh * Dv * NP + (size_t)j * NP + n0 + seg];
        #pragma unroll
        for (int i = 0; i < 32; i += 2) {
            int n = n0 + seg + i;
            if (n + 1 < Nv)
                *reinterpret_cast<__half2*>(dst + i) =
                    *reinterpret_cast<const __half2*>(&sm16[j * 136 + seg + i]);
            else if (n < Nv)
                dst[i] = sm16[j * 136 + seg + i];
        }
    }
}

// ============================================================================
// ctx GEMM (unchanged): C[r][d] = sum_n vt[r,n]*kfT[d,n]; row 64 = ksum.
// ============================================================================
#define CSTG_B 12288
__global__ __launch_bounds__(256)
void ctx_gemm(const __half* __restrict__ vt, const __half* __restrict__ kft,
              __half* __restrict__ ctxh) {
    __shared__ char csm[4 * CSTG_B];
    const uint32_t base = s2u(csm);
    const int tid = threadIdx.x, warp = tid >> 5, lane = tid & 31;
    const int bh = blockIdx.x;
    const __half* Av = vt  + (size_t)bh * 72 * NP;
    const __half* Bk = kft + (size_t)bh * Dv * NP;
    const int nk = NP / 32;

    auto stage = [&](int t, int sb) {
        const int k0 = t * 32;
        const uint32_t sbase = base + sb * CSTG_B;
        #pragma unroll
        for (int l = 0; l < 3; ++l) {
            int idx = tid + l * 256;
            if (idx < 512) {
                int r = idx >> 2, s = idx & 3;
                int ok = (r < 72);
                cp16p(sbase + chunk_off(s, r),
                      Av + (size_t)(ok ? r : 0) * NP + k0 + s * 8, ok ? 16 : 0);
            } else {
                int j = idx - 512;
                int r = j >> 2, s = j & 3;
                cp16(sbase + 8192 + chunk_off64(s, r),
                     Bk + (size_t)r * NP + k0 + s * 8);
            }
        }
    };

    stage(0, 0); CPCOMMIT();
    stage(1, 1); CPCOMMIT();
    stage(2, 2); CPCOMMIT();

    const int wm = (warp >> 1) * 32, wn = (warp & 1) * 32;
    const int a_r = lane & 15, a_s = lane >> 4;
    const int b_r = lane & 7,  b_s = (lane >> 3) & 1;
    float acc[2][4][4];
    #pragma unroll
    for (int i = 0; i < 2; ++i)
        #pragma unroll
        for (int j = 0; j < 4; ++j)
            #pragma unroll
            for (int c = 0; c < 4; ++c) acc[i][j][c] = 0.f;

    for (int t = 0; t < nk; ++t) {
        cpwait(min(nk - 1 - t, 2));
        __syncthreads();
        const uint32_t pb = base + (t & 3) * CSTG_B;
        #pragma unroll
        for (int ks = 0; ks < 2; ++ks) {
            uint32_t af[2][4], bf[4][2];
            #pragma unroll
            for (int ni = 0; ni < 4; ++ni)
                ldm2(bf[ni], pb + 8192 + chunk_off64(2 * ks + b_s, wn + ni * 8 + b_r));
            #pragma unroll
            for (int mi = 0; mi < 2; ++mi)
                ldm4(af[mi], pb + chunk_off(2 * ks + a_s, wm + mi * 16 + a_r));
            #pragma unroll
            for (int mi = 0; mi < 2; ++mi)
                #pragma unroll
                for (int ni = 0; ni < 4; ++ni)
                    mma16816(acc[mi][ni], af[mi], bf[ni]);
        }
        __syncthreads();
        if (t + 3 < nk) { stage(t + 3, (t + 3) & 3); CPCOMMIT(); }
    }

    const int er = lane >> 2, ec = 2 * (lane & 3);
    #pragma unroll
    for (int mi = 0; mi < 2; ++mi)
        #pragma unroll
        for (int ni = 0; ni < 4; ++ni) {
            int row = wm + mi * 16 + er, col = wn + ni * 8 + ec;
            if (row < 72)
                *reinterpret_cast<__half2*>(&ctxh[(size_t)bh * 128 * Dv + row * Dv + col]) =
                    __floats2half2_rn(acc[mi][ni][0], acc[mi][ni][1]);
            if (row + 8 < 72)
                *reinterpret_cast<__half2*>(&ctxh[(size_t)bh * 128 * Dv + (row + 8) * Dv + col]) =
                    __floats2half2_rn(acc[mi][ni][2], acc[mi][ni][3]);
        }
}

// ============================================================================
// out GEMM (unchanged): col64 = denom; divide in epilogue -> ah fp16
// ============================================================================
__global__ __launch_bounds__(256)
void out_gemm(const __half* __restrict__ qf, const __half* __restrict__ ctxh,
              __half* __restrict__ ah) {
    __shared__ char osm[32768];
    __shared__ float sden[128];
    const uint32_t base = s2u(osm), bB = base + 16384;
    const int tid = threadIdx.x, warp = tid >> 5, lane = tid & 31;
    const int n0 = blockIdx.x * 128, bh = blockIdx.y;
    const int b = bh / Hv, h = bh % Hv;
    const __half* A = qf   + (size_t)bh * Nv * Dv;
    const __half* Bm = ctxh + (size_t)bh * 128 * Dv;

    #pragma unroll
    for (int l = 0; l < 4; ++l) {
        int idx = tid + l * 256;
        int r = idx >> 3, s = idx & 7;
        int n = n0 + r, ok = (n < Nv);
        cp16p(base + chunk_off(s, r), A + (size_t)(ok ? n : 0) * Dv + s * 8, ok ? 16 : 0);
    }
    #pragma unroll
    for (int l = 0; l < 4; ++l) {
        int idx = tid + l * 256;
        int r = idx >> 3, s = idx & 7;
        cp16(bB + chunk_off(s, r), Bm + (size_t)r * Dv + s * 8);
    }
    CPCOMMIT(); cpwait(0); __syncthreads();

    const int wm = (warp >> 2) * 64, wn = (warp & 3) * 32;
    const int a_r = lane & 15, a_s = lane >> 4;
    const int b_r = lane & 7,  b_s = (lane >> 3) & 1;
    float acc[4][4][4];
    #pragma unroll
    for (int i = 0; i < 4; ++i)
        #pragma unroll
        for (int j = 0; j < 4; ++j)
            #pragma unroll
            for (int c = 0; c < 4; ++c) acc[i][j][c] = 0.f;

    #pragma unroll
    for (int ks = 0; ks < 4; ++ks) {
        uint32_t af[4][4], bf[4][2];
        #pragma unroll
        for (int ni = 0; ni < 4; ++ni)
            ldm2(bf[ni], bB + chunk_off(2 * ks + b_s, wn + ni * 8 + b_r));
        #pragma unroll
        for (int mi = 0; mi < 4; ++mi)
            ldm4(af[mi], base + chunk_off(2 * ks + a_s, wm + mi * 16 + a_r));
        #pragma unroll
        for (int mi = 0; mi < 4; ++mi)
            #pragma unroll
            for (int ni = 0; ni < 4; ++ni)
                mma16816(acc[mi][ni], af[mi], bf[ni]);
    }

    const int er = lane >> 2, ec = 2 * (lane & 3);
    if (wn == 64 && (lane & 3) == 0) {
        #pragma unroll
        for (int mi = 0; mi < 4; ++mi) {
            sden[wm + mi * 16 + er]     = acc[mi][0][0];
            sden[wm + mi * 16 + er + 8] = acc[mi][0][2];
        }
    }
    __syncthreads();
    if (wn < 64) {
        #pragma unroll
        for (int mi = 0; mi < 4; ++mi)
            #pragma unroll
            for (int ni = 0; ni < 4; ++ni) {
                int row = wm + mi * 16 + er, col = wn + ni * 8 + ec;
                int n = n0 + row;
                if (n < Nv) {
                    float inv = 1.f / sden[row];
                    *reinterpret_cast<__half2*>(
                        &ah[((size_t)(b * Nv + n)) * DIMv + h * Dv + col]) =
                        __floats2half2_rn(acc[mi][ni][0] * inv, acc[mi][ni][1] * inv);
                }
                if (n + 8 < Nv) {
                    float inv = 1.f / sden[row + 8];
                    *reinterpret_cast<__half2*>(
                        &ah[((size_t)(b * Nv + n + 8)) * DIMv + h * Dv + col]) =
                        __floats2half2_rn(acc[mi][ni][2] * inv, acc[mi][ni][3] * inv);
                }
            }
    }
}

// ============================================================================
// launcher
// ============================================================================
extern "C" void kernel_launch(void* const* d_in, const int* in_sizes, int n_in,
                              void* d_out, int out_size) {
    const float* x     = (const float*)d_in[0];
    const float* W_qkv = (const float*)d_in[1];
    const float* W_out = (const float*)d_in[2];
    const float* b_out = (const float*)d_in[3];
    const float* proj  = (const float*)d_in[4];
    const float* fcos  = (const float*)d_in[5];
    const float* fsin  = (const float*)d_in[6];
    float* out = (float*)d_out;

    __half *xh, *wqh, *woh, *projh, *qh, *kh, *vtmp, *vt, *qfh, *kft, *ctxh, *ah;
    cudaGetSymbolAddress((void**)&xh,    g_xh);
    cudaGetSymbolAddress((void**)&wqh,   g_wqh);
    cudaGetSymbolAddress((void**)&woh,   g_woh);
    cudaGetSymbolAddress((void**)&projh, g_projh);
    cudaGetSymbolAddress((void**)&qh,    g_qh);
    cudaGetSymbolAddress((void**)&kh,    g_kh);
    cudaGetSymbolAddress((void**)&vtmp,  g_vtmp);
    cudaGetSymbolAddress((void**)&vt,    g_vt);
    cudaGetSymbolAddress((void**)&qfh,   g_qfh);
    cudaGetSymbolAddress((void**)&kft,   g_kft);
    cudaGetSymbolAddress((void**)&ctxh,  g_ctxh);
    cudaGetSymbolAddress((void**)&ah,    g_ah);

    cudaFuncSetAttribute(gemm_qkv,
                         cudaFuncAttributeMaxDynamicSharedMemorySize, GSMEM);
    cudaFuncSetAttribute(gemm_out,
                         cudaFuncAttributeMaxDynamicSharedMemorySize, GSMEM);

    // 0) conversions
    conv_fp16<<<2048, 256>>>(x,     xh,  (size_t)M1 * DIMv / 4);
    conv_fp16<<<512,  256>>>(W_qkv, wqh, (size_t)G3 * DIMv / 4);
    conv_fp16<<<256,  256>>>(W_out, woh, (size_t)DIMv * DIMv / 4);
    conv_proj<<<16,   256>>>(proj, projh);

    // 1) QKV projection with fused RoPE -> qh, kh, vtmp (all fp16)
    {
        dim3 grid(G3 / 128, (M1 + 127) / 128);
        gemm_qkv<<<grid, 256, GSMEM>>>(xh, wqh, fcos, fsin, qh, kh, vtmp);
    }
    // 2) v transpose + ones row
    {
        dim3 grid(33, BH);
        vtrans<<<grid, 256>>>(vtmp, vt);
    }
    // 3) feature maps (HMMA)
    {
        dim3 grid(9, BH, 2);
        feat_gemm<<<grid, 256>>>(qh, kh, projh, qfh, kft);
    }
    // 4) context + ksum (HMMA, ones-row trick)
    ctx_gemm<<<BH, 256>>>(vt, kft, ctxh);
    // 5) output contraction + divide -> ah fp16
    {
        dim3 grid(9, BH);
        out_gemm<<<grid, 256>>>(qfh, ctxh, ah);
    }
    // 6) output projection + bias
    {
        dim3 grid(DIMv / 128, (M1 + 127) / 128);
        gemm_out<<<grid, 256, GSMEM>>>(ah, woh, b_out, out, M1, DIMv, DIMv);
    }
}